// round 2
// baseline (speedup 1.0000x reference)
#include <cuda_runtime.h>

#define NN 1024
#define LL 64

// scratch (allocation-free rule: device globals)
__device__ float g_preib[NN * LL];   // pre_i + be1
__device__ float g_prej [NN * LL];   // pre_j
__device__ float g_V    [NN];
__device__ float g_newH [NN * LL];
__device__ float g_part [16 * LL];   // partial Hsum

// fast, accurate-enough tanh: 1 - 2/(exp(2x)+1)
__device__ __forceinline__ float ftanh(float x) {
    float e = __expf(2.0f * x);
    return 1.0f - __fdividef(2.0f, e + 1.0f);
}

// packed fp32x2 FMA (Blackwell; PTX-only, ptxas never auto-fuses)
__device__ __forceinline__ unsigned long long ffma2(unsigned long long a,
                                                    unsigned long long b,
                                                    unsigned long long c) {
    unsigned long long d;
    asm("fma.rn.f32x2 %0, %1, %2, %3;" : "=l"(d) : "l"(a), "l"(b), "l"(c));
    return d;
}
__device__ __forceinline__ unsigned long long pk2(float lo, float hi) {
    return (unsigned long long)__float_as_uint(lo) |
           ((unsigned long long)__float_as_uint(hi) << 32);
}
__device__ __forceinline__ float lo32(unsigned long long v) { return __uint_as_float((unsigned)v); }
__device__ __forceinline__ float hi32(unsigned long long v) { return __uint_as_float((unsigned)(v >> 32)); }

// ---------------------------------------------------------------------------
// Kernel A: H = LM[cat]; preib = H @ We1[:L] + be1 ; prej = H @ We1[L:2L]
// ---------------------------------------------------------------------------
__global__ void prep_kernel(const int* __restrict__ cats,
                            const float* __restrict__ LM,
                            const float* __restrict__ We1,
                            const float* __restrict__ be1) {
    __shared__ float Hs[LL];
    int n = blockIdx.x, l = threadIdx.x;
    Hs[l] = LM[cats[n] * LL + l];
    __syncthreads();
    float ai = be1[l], aj = 0.0f;
#pragma unroll
    for (int k = 0; k < LL; k++) {
        float h = Hs[k];
        ai = fmaf(h, We1[k * LL + l], ai);
        aj = fmaf(h, We1[(LL + k) * LL + l], aj);
    }
    g_preib[n * LL + l] = ai;
    g_prej[n * LL + l] = aj;
}

// ---------------------------------------------------------------------------
// Kernel B: the O(N^2 * L^2) pair loop (dominant cost).
// Block = atom i. 8 warps; warp w streams j = w, w+8, ...
// Phase 1: h1[64] = tanh(pre_i + pre_j + d2*w1z + be1) -> warp-private smem
//          (double buffered, one __syncwarp per pair).
// Phase 2: y = tanh(h1 @ We2 + be2), summed into V. We2 held in registers,
//          packed along k as f32x2 so the h-operand pairs come straight out
//          of 128-bit smem loads (no pack instructions). 64 FFMA2 per pair.
// j == i excluded (equivalent to total - diag).
// ---------------------------------------------------------------------------
__global__ __launch_bounds__(256, 1)
void pair_kernel(const float* __restrict__ coords,
                 const float* __restrict__ We1,
                 const float* __restrict__ We2,
                 const float* __restrict__ be2) {
    __shared__ float s_preib[LL];
    __shared__ float s_w1z[LL];
    __shared__ float s_coord[NN * 3];
    __shared__ __align__(16) float s_h1[8][2][LL];
    __shared__ float s_red[8];

    const int i = blockIdx.x;
    const int t = threadIdx.x;
    const int w = t >> 5, lane = t & 31;
    const int c0 = 2 * lane, c1 = c0 + 1;

    // We2 columns c0,c1 packed along k: wa[q] = (We2[2q][c0], We2[2q+1][c0])
    unsigned long long wa[32], wb[32];
#pragma unroll
    for (int q = 0; q < 32; q++) {
        wa[q] = pk2(We2[(2 * q) * LL + c0], We2[(2 * q + 1) * LL + c0]);
        wb[q] = pk2(We2[(2 * q) * LL + c1], We2[(2 * q + 1) * LL + c1]);
    }
    const float be2a = be2[c0];
    const float be2b = be2[c1];

    if (t < LL) {
        s_preib[t] = g_preib[i * LL + t];
        s_w1z[t]   = We1[2 * LL * LL + t];   // w1z = We1 row 128
    }
    for (int idx = t; idx < NN * 3; idx += 256)
        s_coord[idx] = coords[idx];
    __syncthreads();

    const float zx = s_coord[3 * i], zy = s_coord[3 * i + 1], zz = s_coord[3 * i + 2];
    const float pA  = s_preib[lane], pB  = s_preib[lane + 32];
    const float wzA = s_w1z[lane],   wzB = s_w1z[lane + 32];

    float vpart = 0.0f;
    int buf = 0;

    for (int j = w; j < NN; j += 8) {
        // phase 1: h1 (lane covers k = lane and k = lane+32)
        float dx = zx - s_coord[3 * j];
        float dy = zy - s_coord[3 * j + 1];
        float dz = zz - s_coord[3 * j + 2];
        float d2 = dx * dx + dy * dy + dz * dz;
        float s0 = pA + g_prej[j * LL + lane]      + d2 * wzA;
        float s1 = pB + g_prej[j * LL + 32 + lane] + d2 * wzB;
        s_h1[w][buf][lane]      = ftanh(s0);
        s_h1[w][buf][lane + 32] = ftanh(s1);
        __syncwarp();

        // phase 2: 64x64 matvec as 64 FFMA2, 4 independent chains
        unsigned long long a0 = 0ull, a1 = 0ull, b0 = 0ull, b1 = 0ull;
#pragma unroll
        for (int p = 0; p < 16; p++) {
            ulonglong2 h = *reinterpret_cast<const ulonglong2*>(&s_h1[w][buf][4 * p]);
            a0 = ffma2(h.x, wa[2 * p],     a0);
            b0 = ffma2(h.x, wb[2 * p],     b0);
            a1 = ffma2(h.y, wa[2 * p + 1], a1);
            b1 = ffma2(h.y, wb[2 * p + 1], b1);
        }
        if (j != i) {
            float ya = lo32(a0) + hi32(a0) + lo32(a1) + hi32(a1) + be2a;
            float yb = lo32(b0) + hi32(b0) + lo32(b1) + hi32(b1) + be2b;
            vpart += ftanh(ya) + ftanh(yb);
        }
        buf ^= 1;
    }

    // reduce V over warp + block
#pragma unroll
    for (int o = 16; o > 0; o >>= 1)
        vpart += __shfl_down_sync(0xffffffffu, vpart, o);
    if (lane == 0) s_red[w] = vpart;
    __syncthreads();
    if (t == 0) {
        float v = 0.f;
#pragma unroll
        for (int q = 0; q < 8; q++) v += s_red[q];
        g_V[i] = v;
    }
}

// ---------------------------------------------------------------------------
// Kernel C1: hh = tanh(H@Wh1[:L] + V*Wh1[L] + bh1); newH = tanh(hh@Wh2 + bh2)
// ---------------------------------------------------------------------------
__global__ void head_kernel(const int* __restrict__ cats,
                            const float* __restrict__ LM,
                            const float* __restrict__ Wh1,
                            const float* __restrict__ bh1,
                            const float* __restrict__ Wh2,
                            const float* __restrict__ bh2) {
    __shared__ float Hs[LL];
    __shared__ float hhs[LL];
    int n = blockIdx.x, l = threadIdx.x;
    Hs[l] = LM[cats[n] * LL + l];
    __syncthreads();
    float V = g_V[n];
    float acc = fmaf(V, Wh1[LL * LL + l], bh1[l]);   // Wh1 row L
#pragma unroll
    for (int k = 0; k < LL; k++)
        acc = fmaf(Hs[k], Wh1[k * LL + l], acc);
    hhs[l] = tanhf(acc);
    __syncthreads();
    float acc2 = bh2[l];
#pragma unroll
    for (int k = 0; k < LL; k++)
        acc2 = fmaf(hhs[k], Wh2[k * LL + l], acc2);
    g_newH[n * LL + l] = tanhf(acc2);
}

// ---------------------------------------------------------------------------
// Kernel C2a: partial column sums of newH (16 blocks, coalesced)
// ---------------------------------------------------------------------------
__global__ void final1_kernel() {
    __shared__ float s[256];
    int b = blockIdx.x, t = threadIdx.x;
    int l = t & 63, r = t >> 6;
    float acc = 0.f;
#pragma unroll
    for (int m = 0; m < 16; m++) {
        int n = b * 64 + r * 16 + m;
        acc += g_newH[n * LL + l];
    }
    s[t] = acc;
    __syncthreads();
    if (t < 64)
        g_part[b * LL + t] = s[t] + s[t + 64] + s[t + 128] + s[t + 192];
}

// ---------------------------------------------------------------------------
// Kernel C2b: Hsum = sum of partials; out = Hsum @ Wo + bo
// ---------------------------------------------------------------------------
__global__ void final2_kernel(const float* __restrict__ Wo,
                              const float* __restrict__ bo,
                              float* __restrict__ out) {
    __shared__ float s_w[2];
    int t = threadIdx.x;          // 64 threads
    float h = 0.f;
#pragma unroll
    for (int q = 0; q < 16; q++)
        h += g_part[q * LL + t];
    float v = h * Wo[t];
#pragma unroll
    for (int o = 16; o > 0; o >>= 1)
        v += __shfl_down_sync(0xffffffffu, v, o);
    if ((t & 31) == 0) s_w[t >> 5] = v;
    __syncthreads();
    if (t == 0) out[0] = s_w[0] + s_w[1] + bo[0];
}

// ---------------------------------------------------------------------------
extern "C" void kernel_launch(void* const* d_in, const int* in_sizes, int n_in,
                              void* d_out, int out_size) {
    (void)in_sizes; (void)n_in; (void)out_size;
    const int*   cats   = (const int*)  d_in[0];
    const float* coords = (const float*)d_in[1];
    const float* LM     = (const float*)d_in[2];
    const float* We1    = (const float*)d_in[3];
    const float* be1    = (const float*)d_in[4];
    const float* We2    = (const float*)d_in[5];
    const float* be2    = (const float*)d_in[6];
    const float* Wh1    = (const float*)d_in[7];
    const float* bh1    = (const float*)d_in[8];
    const float* Wh2    = (const float*)d_in[9];
    const float* bh2    = (const float*)d_in[10];
    const float* Wo     = (const float*)d_in[11];
    const float* bo     = (const float*)d_in[12];

    prep_kernel  <<<NN, LL >>>(cats, LM, We1, be1);
    pair_kernel  <<<NN, 256>>>(coords, We1, We2, be2);
    head_kernel  <<<NN, LL >>>(cats, LM, Wh1, bh1, Wh2, bh2);
    final1_kernel<<<16, 256>>>();
    final2_kernel<<<1,  64 >>>(Wo, bo, (float*)d_out);
}

// round 4
// speedup vs baseline: 1.8399x; 1.8399x over previous
#include <cuda_runtime.h>
#include <cuda_bf16.h>
#include <cstdint>

#define NN 1024
#define LL 64

// scratch (allocation-free rule: device globals)
__device__ __align__(16) float g_preib[NN * LL];   // pre_i + be1
__device__ __align__(16) float g_prej [NN * LL];   // pre_j
__device__ float g_V[NN];
__device__ __align__(16) float g_newH[NN * LL];
__device__ float g_part[16 * LL];

// fast accurate tanh: 1 - 2/(exp(2x)+1)   (rel err ~1e-6, saturates correctly)
__device__ __forceinline__ float ftanh(float x) {
    float e = __expf(2.0f * x);
    return 1.0f - __fdividef(2.0f, e + 1.0f);
}

__device__ __forceinline__ uint32_t smem_u32(const void* p) {
    uint32_t a;
    asm("{ .reg .u64 t; cvta.to.shared.u64 t, %1; cvt.u32.u64 %0, t; }" : "=r"(a) : "l"(p));
    return a;
}
__device__ __forceinline__ void ldsm4(uint32_t* r, uint32_t addr) {
    asm volatile("ldmatrix.sync.aligned.m8n8.x4.shared.b16 {%0,%1,%2,%3}, [%4];"
                 : "=r"(r[0]), "=r"(r[1]), "=r"(r[2]), "=r"(r[3]) : "r"(addr));
}
__device__ __forceinline__ void ldsm2(uint32_t* r, uint32_t addr) {
    asm volatile("ldmatrix.sync.aligned.m8n8.x2.shared.b16 {%0,%1}, [%2];"
                 : "=r"(r[0]), "=r"(r[1]) : "r"(addr));
}
__device__ __forceinline__ void mma16816(float* c, const uint32_t* a, const uint32_t* b) {
    asm volatile(
        "mma.sync.aligned.m16n8k16.row.col.f32.bf16.bf16.f32 "
        "{%0,%1,%2,%3},{%4,%5,%6,%7},{%8,%9},{%0,%1,%2,%3};"
        : "+f"(c[0]), "+f"(c[1]), "+f"(c[2]), "+f"(c[3])
        : "r"(a[0]), "r"(a[1]), "r"(a[2]), "r"(a[3]), "r"(b[0]), "r"(b[1]));
}
__device__ __forceinline__ uint32_t pkbf2(float a, float b) {
    __nv_bfloat162 h = __floats2bfloat162_rn(a, b);
    return *reinterpret_cast<uint32_t*>(&h);
}

// dynamic smem layout (offsets from 1024-aligned base)
#define OFF_A     0u          // 8 warps x (2KB hi + 2KB lo) = 32KB
#define OFF_BLO   32768u      // 8KB  (B-lo bf16, [n][k] swizzled)
#define OFF_W2S   40960u      // 16KB (We2 fp32 staging)
#define OFF_COORD 57344u      // 12KB
#define OFF_PREIB 69632u
#define OFF_W1Z   69888u
#define OFF_BE2   70144u
#define DYN_BYTES (70400u + 1024u)

// ---------------------------------------------------------------------------
// Kernel A: H = LM[cat]; preib = H @ We1[:L] + be1 ; prej = H @ We1[L:2L]
// ---------------------------------------------------------------------------
__global__ void prep_kernel(const int* __restrict__ cats,
                            const float* __restrict__ LM,
                            const float* __restrict__ We1,
                            const float* __restrict__ be1) {
    __shared__ float Hs[LL];
    int n = blockIdx.x, l = threadIdx.x;
    Hs[l] = LM[cats[n] * LL + l];
    __syncthreads();
    float ai = be1[l], aj = 0.0f;
#pragma unroll
    for (int k = 0; k < LL; k++) {
        float h = Hs[k];
        ai = fmaf(h, We1[k * LL + l], ai);
        aj = fmaf(h, We1[(LL + k) * LL + l], aj);
    }
    g_preib[n * LL + l] = ai;
    g_prej[n * LL + l] = aj;
}

// ---------------------------------------------------------------------------
// Kernel B: block = atom i, 8 warps. Warp w owns j in [w*128, w*128+128),
// processed as 8 tiles of 16 j-rows.
//   phase 1: h1 = tanh(pre_i + pre_j + d2*w1z + be1), split bf16 hi+lo into
//            warp-private swizzled smem (16x64 each).
//   phase 2: mma.sync m16n8k16 bf16: C += Ahi*Bhi + Alo*Bhi + Ahi*Blo
//            (fp32 accum; ~4e-6 product error). B-hi in regs, B-lo via LDSM.
//   epilogue: vpart += tanh(C + be2), skipping j == i.
// ---------------------------------------------------------------------------
__global__ __launch_bounds__(256, 1)
void pair_kernel(const float* __restrict__ coords,
                 const float* __restrict__ We1,
                 const float* __restrict__ We2,
                 const float* __restrict__ be2) {
    extern __shared__ __align__(16) char dyn_raw[];
    char* base = (char*)((((uintptr_t)dyn_raw) + 1023) & ~(uintptr_t)1023);
    const uint32_t sb = smem_u32(base);

    __shared__ float s_red[8];

    float* s_coord = (float*)(base + OFF_COORD);
    float* s_preib = (float*)(base + OFF_PREIB);
    float* s_w1z   = (float*)(base + OFF_W1Z);
    float* s_be2   = (float*)(base + OFF_BE2);
    float* We2s    = (float*)(base + OFF_W2S);

    const int i = blockIdx.x;
    const int t = threadIdx.x;
    const int w = t >> 5, lane = t & 31;

    // ---- stage We2 (fp32), coords, vectors ----
    for (int idx = t; idx < LL * LL; idx += 256) We2s[idx] = We2[idx];
    for (int idx = t; idx < 3 * NN; idx += 256) s_coord[idx] = coords[idx];
    if (t < LL) {
        s_preib[t] = g_preib[i * LL + t];
        s_w1z[t]   = We1[2 * LL * LL + t];
        s_be2[t]   = be2[t];
    }
    __syncthreads();

    // ---- B-lo smem: Blo[n][k] = residual(We2[k][n]), SW128 swizzled ----
    for (int idx = t; idx < LL * LL; idx += 256) {
        int n = idx >> 6, k = idx & 63;
        float f = We2s[k * LL + n];
        __nv_bfloat16 hi = __float2bfloat16(f);
        __nv_bfloat16 lo = __float2bfloat16(f - __bfloat162float(hi));
        uint32_t o = (uint32_t)(n * 128 + 2 * k);
        o = o ^ ((o >> 3) & 0x70);
        *(__nv_bfloat16*)(base + OFF_BLO + o) = lo;
    }

    // ---- B-hi fragments in registers: bhi[nt][kk][2] ----
    uint32_t bhi[8][4][2];
    {
        const int n  = (lane >> 2);           // + nt*8
        const int kq = 2 * (lane & 3);        // + kk*16 (+8 for reg1)
#pragma unroll
        for (int nt = 0; nt < 8; nt++)
#pragma unroll
            for (int kk = 0; kk < 4; kk++) {
                int k0 = kk * 16 + kq, nn = nt * 8 + n;
                bhi[nt][kk][0] = pkbf2(We2s[(k0)     * LL + nn], We2s[(k0 + 1) * LL + nn]);
                bhi[nt][kk][1] = pkbf2(We2s[(k0 + 8) * LL + nn], We2s[(k0 + 9) * LL + nn]);
            }
    }
    // be2 per epilogue column
    float be2v[8][2];
    {
        const int cb = 2 * (lane & 3);
#pragma unroll
        for (int nt = 0; nt < 8; nt++) {
            be2v[nt][0] = s_be2[nt * 8 + cb];
            be2v[nt][1] = s_be2[nt * 8 + cb + 1];
        }
    }
    __syncthreads();

    const float zx = s_coord[3 * i], zy = s_coord[3 * i + 1], zz = s_coord[3 * i + 2];

    // phase-1 lane mapping: row r = lane/2, k-half ks = (lane&1)*32
    const int r1  = lane >> 1;
    const int ks  = (lane & 1) * 32;
    const uint32_t xorS = (uint32_t)((r1 & 7) << 4);
    char* AH = base + OFF_A + w * 4096;       // hi tile; lo at +2048

    // ldmatrix A lane mapping
    const int rowA = (lane & 7) + ((lane >> 3) & 1) * 8;
    const uint32_t m16A  = (uint32_t)((lane >> 4) * 16);
    const uint32_t xorA  = (uint32_t)((rowA & 7) << 4);
    const uint32_t abHi  = sb + OFF_A + (uint32_t)w * 4096u + (uint32_t)rowA * 128u;
    // ldmatrix B-lo lane mapping
    const int l16 = lane & 15;
    const uint32_t kh16 = (uint32_t)((l16 >> 3) * 16);
    const uint32_t xorB = (uint32_t)((l16 & 7) << 4);
    const uint32_t bbLo = sb + OFF_BLO + (uint32_t)(l16 & 7) * 128u;

    // epilogue mapping
    const int row0 = lane >> 2;

    float vpart = 0.0f;

    for (int tile = 0; tile < 8; tile++) {
        const int jbase = w * 128 + tile * 16;
        __syncwarp();
        // ---------------- phase 1 ----------------
        {
            const int j = jbase + r1;
            float dx = zx - s_coord[3 * j];
            float dy = zy - s_coord[3 * j + 1];
            float dz = zz - s_coord[3 * j + 2];
            float d2 = dx * dx + dy * dy + dz * dz;
            const float4* pj = (const float4*)(g_prej + j * LL + ks);
#pragma unroll
            for (int p8 = 0; p8 < 4; p8++) {
                float4 u = pj[p8 * 2], v = pj[p8 * 2 + 1];
                const int k0 = ks + p8 * 8;
                float pv[8] = {u.x, u.y, u.z, u.w, v.x, v.y, v.z, v.w};
                uint4 HI, LO;
                uint32_t* hp = (uint32_t*)&HI;
                uint32_t* lp = (uint32_t*)&LO;
#pragma unroll
                for (int q = 0; q < 4; q++) {
                    float2 pr = *(const float2*)&s_preib[k0 + 2 * q];
                    float2 wz = *(const float2*)&s_w1z[k0 + 2 * q];
                    float h0 = ftanh(fmaf(d2, wz.x, pr.x + pv[2 * q]));
                    float h1 = ftanh(fmaf(d2, wz.y, pr.y + pv[2 * q + 1]));
                    __nv_bfloat162 hh = __floats2bfloat162_rn(h0, h1);
                    hp[q] = *reinterpret_cast<uint32_t*>(&hh);
                    float l0 = h0 - __bfloat162float(hh.x);
                    float l1 = h1 - __bfloat162float(hh.y);
                    lp[q] = pkbf2(l0, l1);
                }
                uint32_t o = (uint32_t)(r1 * 128) + (((uint32_t)(k0 * 2)) ^ xorS);
                *(uint4*)(AH + o)        = HI;
                *(uint4*)(AH + 2048 + o) = LO;
            }
        }
        __syncwarp();
        // ---------------- phase 2 ----------------
        uint32_t ahi[4][4], alo[4][4];
#pragma unroll
        for (int kk = 0; kk < 4; kk++) {
            uint32_t o = (m16A + (uint32_t)(kk * 32)) ^ xorA;
            ldsm4(ahi[kk], abHi + o);
            ldsm4(alo[kk], abHi + 2048u + o);
        }
        const bool mytile = (jbase <= i) && (i < jbase + 16);
        const int rowi = i - jbase;
#pragma unroll
        for (int ntp = 0; ntp < 4; ntp++) {
            const int n0 = 2 * ntp, n1 = n0 + 1;
            float c0[4] = {0.f, 0.f, 0.f, 0.f};
            float c1[4] = {0.f, 0.f, 0.f, 0.f};
#pragma unroll
            for (int kk = 0; kk < 4; kk++) {
                uint32_t bl0[2], bl1[2];
                ldsm2(bl0, bbLo + (uint32_t)(n0 * 1024) + (((uint32_t)(kk * 32) + kh16) ^ xorB));
                ldsm2(bl1, bbLo + (uint32_t)(n1 * 1024) + (((uint32_t)(kk * 32) + kh16) ^ xorB));
                mma16816(c0, ahi[kk], bhi[n0][kk]);
                mma16816(c1, ahi[kk], bhi[n1][kk]);
                mma16816(c0, alo[kk], bhi[n0][kk]);
                mma16816(c1, alo[kk], bhi[n1][kk]);
                mma16816(c0, ahi[kk], bl0);
                mma16816(c1, ahi[kk], bl1);
            }
            // epilogue for nt = n0, n1
            float acc0 = ftanh(c0[0] + be2v[n0][0]) + ftanh(c0[1] + be2v[n0][1])
                       + ftanh(c1[0] + be2v[n1][0]) + ftanh(c1[1] + be2v[n1][1]);
            float acc1 = ftanh(c0[2] + be2v[n0][0]) + ftanh(c0[3] + be2v[n0][1])
                       + ftanh(c1[2] + be2v[n1][0]) + ftanh(c1[3] + be2v[n1][1]);
            if (!(mytile && row0 == rowi))     vpart += acc0;
            if (!(mytile && row0 + 8 == rowi)) vpart += acc1;
        }
    }

    // reduce V over warp + block
#pragma unroll
    for (int o = 16; o > 0; o >>= 1)
        vpart += __shfl_down_sync(0xffffffffu, vpart, o);
    if (lane == 0) s_red[w] = vpart;
    __syncthreads();
    if (t == 0) {
        float v = 0.f;
#pragma unroll
        for (int q = 0; q < 8; q++) v += s_red[q];
        g_V[i] = v;
    }
}

// ---------------------------------------------------------------------------
// Kernel C1: hh = tanh(H@Wh1[:L] + V*Wh1[L] + bh1); newH = tanh(hh@Wh2 + bh2)
// ---------------------------------------------------------------------------
__global__ void head_kernel(const int* __restrict__ cats,
                            const float* __restrict__ LM,
                            const float* __restrict__ Wh1,
                            const float* __restrict__ bh1,
                            const float* __restrict__ Wh2,
                            const float* __restrict__ bh2) {
    __shared__ float Hs[LL];
    __shared__ float hhs[LL];
    int n = blockIdx.x, l = threadIdx.x;
    Hs[l] = LM[cats[n] * LL + l];
    __syncthreads();
    float V = g_V[n];
    float acc = fmaf(V, Wh1[LL * LL + l], bh1[l]);
#pragma unroll
    for (int k = 0; k < LL; k++)
        acc = fmaf(Hs[k], Wh1[k * LL + l], acc);
    hhs[l] = tanhf(acc);
    __syncthreads();
    float acc2 = bh2[l];
#pragma unroll
    for (int k = 0; k < LL; k++)
        acc2 = fmaf(hhs[k], Wh2[k * LL + l], acc2);
    g_newH[n * LL + l] = tanhf(acc2);
}

// ---------------------------------------------------------------------------
__global__ void final1_kernel() {
    __shared__ float s[256];
    int b = blockIdx.x, t = threadIdx.x;
    int l = t & 63, r = t >> 6;
    float acc = 0.f;
#pragma unroll
    for (int m = 0; m < 16; m++) {
        int n = b * 64 + r * 16 + m;
        acc += g_newH[n * LL + l];
    }
    s[t] = acc;
    __syncthreads();
    if (t < 64)
        g_part[b * LL + t] = s[t] + s[t + 64] + s[t + 128] + s[t + 192];
}

__global__ void final2_kernel(const float* __restrict__ Wo,
                              const float* __restrict__ bo,
                              float* __restrict__ out) {
    __shared__ float s_w[2];
    int t = threadIdx.x;          // 64 threads
    float h = 0.f;
#pragma unroll
    for (int q = 0; q < 16; q++)
        h += g_part[q * LL + t];
    float v = h * Wo[t];
#pragma unroll
    for (int o = 16; o > 0; o >>= 1)
        v += __shfl_down_sync(0xffffffffu, v, o);
    if ((t & 31) == 0) s_w[t >> 5] = v;
    __syncthreads();
    if (t == 0) out[0] = s_w[0] + s_w[1] + bo[0];
}

// ---------------------------------------------------------------------------
extern "C" void kernel_launch(void* const* d_in, const int* in_sizes, int n_in,
                              void* d_out, int out_size) {
    (void)in_sizes; (void)n_in; (void)out_size;
    const int*   cats   = (const int*)  d_in[0];
    const float* coords = (const float*)d_in[1];
    const float* LM     = (const float*)d_in[2];
    const float* We1    = (const float*)d_in[3];
    const float* be1    = (const float*)d_in[4];
    const float* We2    = (const float*)d_in[5];
    const float* be2    = (const float*)d_in[6];
    const float* Wh1    = (const float*)d_in[7];
    const float* bh1    = (const float*)d_in[8];
    const float* Wh2    = (const float*)d_in[9];
    const float* bh2    = (const float*)d_in[10];
    const float* Wo     = (const float*)d_in[11];
    const float* bo     = (const float*)d_in[12];

    cudaFuncSetAttribute(pair_kernel,
                         cudaFuncAttributeMaxDynamicSharedMemorySize, DYN_BYTES);

    prep_kernel  <<<NN, LL >>>(cats, LM, We1, be1);
    pair_kernel  <<<NN, 256, DYN_BYTES>>>(coords, We1, We2, be2);
    head_kernel  <<<NN, LL >>>(cats, LM, Wh1, bh1, Wh2, bh2);
    final1_kernel<<<16, 256>>>();
    final2_kernel<<<1,  64 >>>(Wo, bo, (float*)d_out);
}

// round 5
// speedup vs baseline: 2.1503x; 1.1687x over previous
#include <cuda_runtime.h>
#include <cuda_bf16.h>
#include <cstdint>

#define NN 1024
#define LL 64

// scratch (allocation-free rule: device globals)
__device__ __align__(16) float g_preib[NN * LL];   // pre_i + be1
__device__ __align__(16) float g_prej [NN * LL];   // pre_j
__device__ float g_V[NN];
__device__ __align__(16) float g_newH[NN * LL];
__device__ float g_part[128 * LL];

// HW tanh: 1 MUFU op (sm_75+), abs err ~5e-4
__device__ __forceinline__ float htanh(float x) {
    float y;
    asm("tanh.approx.f32 %0, %1;" : "=f"(y) : "f"(x));
    return y;
}

__device__ __forceinline__ uint32_t smem_u32(const void* p) {
    uint32_t a;
    asm("{ .reg .u64 t; cvta.to.shared.u64 t, %1; cvt.u32.u64 %0, t; }" : "=r"(a) : "l"(p));
    return a;
}
__device__ __forceinline__ void ldsm4(uint32_t* r, uint32_t addr) {
    asm volatile("ldmatrix.sync.aligned.m8n8.x4.shared.b16 {%0,%1,%2,%3}, [%4];"
                 : "=r"(r[0]), "=r"(r[1]), "=r"(r[2]), "=r"(r[3]) : "r"(addr));
}
__device__ __forceinline__ void mma16816(float* c, const uint32_t* a, const uint32_t* b) {
    asm volatile(
        "mma.sync.aligned.m16n8k16.row.col.f32.bf16.bf16.f32 "
        "{%0,%1,%2,%3},{%4,%5,%6,%7},{%8,%9},{%0,%1,%2,%3};"
        : "+f"(c[0]), "+f"(c[1]), "+f"(c[2]), "+f"(c[3])
        : "r"(a[0]), "r"(a[1]), "r"(a[2]), "r"(a[3]), "r"(b[0]), "r"(b[1]));
}
__device__ __forceinline__ uint32_t pkbf2(float a, float b) {
    __nv_bfloat162 h = __floats2bfloat162_rn(a, b);
    return *reinterpret_cast<uint32_t*>(&h);
}

// dynamic smem layout (offsets from 1024-aligned base)
#define OFF_A     0u          // 8 warps x (2KB hi + 2KB lo) = 32KB
#define OFF_BHI   32768u      // 8KB  (B-hi bf16, [n][k] swizzled)
#define OFF_BLO   40960u      // 8KB  (B-lo residual)
#define OFF_COORD 49152u      // 12KB
#define OFF_PREIB 61440u
#define OFF_W1Z   61696u
#define OFF_BE2   61952u
#define DYN_BYTES (62208u + 1024u)

// ---------------------------------------------------------------------------
// Kernel A: H = LM[cat]; preib = H @ We1[:L] + be1 ; prej = H @ We1[L:2L]
// ---------------------------------------------------------------------------
__global__ void prep_kernel(const int* __restrict__ cats,
                            const float* __restrict__ LM,
                            const float* __restrict__ We1,
                            const float* __restrict__ be1) {
    __shared__ float Hs[LL];
    int n = blockIdx.x, l = threadIdx.x;
    Hs[l] = LM[cats[n] * LL + l];
    __syncthreads();
    float ai = be1[l], aj = 0.0f;
#pragma unroll
    for (int k = 0; k < LL; k++) {
        float h = Hs[k];
        ai = fmaf(h, We1[k * LL + l], ai);
        aj = fmaf(h, We1[(LL + k) * LL + l], aj);
    }
    g_preib[n * LL + l] = ai;
    g_prej[n * LL + l] = aj;
}

// ---------------------------------------------------------------------------
// Kernel B: block = atom i, 8 warps, warp w owns j in [w*128, w*128+128),
// 8 tiles of 16 j-rows. Split-bf16 (hi+lo) mma: C += Ahi*Bhi + Alo*Bhi + Ahi*Blo.
// B hi/lo live in smem (ldsm4 per n-pair); tanh via MUFU.TANH.
// ---------------------------------------------------------------------------
__global__ __launch_bounds__(256, 2)
void pair_kernel(const float* __restrict__ coords,
                 const float* __restrict__ We1,
                 const float* __restrict__ We2,
                 const float* __restrict__ be2) {
    extern __shared__ __align__(16) char dyn_raw[];
    char* base = (char*)((((uintptr_t)dyn_raw) + 1023) & ~(uintptr_t)1023);
    const uint32_t sb = smem_u32(base);

    __shared__ float s_red[8];

    float* s_coord = (float*)(base + OFF_COORD);
    float* s_preib = (float*)(base + OFF_PREIB);
    float* s_w1z   = (float*)(base + OFF_W1Z);
    float* s_be2   = (float*)(base + OFF_BE2);

    const int i = blockIdx.x;
    const int t = threadIdx.x;
    const int w = t >> 5, lane = t & 31;

    // ---- B smem: [n][k] bf16 hi + residual lo, SW128 swizzled, from gmem ----
    for (int idx = t; idx < LL * LL; idx += 256) {
        int n = idx & 63, k = idx >> 6;          // n fastest -> coalesced
        float f = We2[k * LL + n];
        __nv_bfloat16 hi = __float2bfloat16(f);
        __nv_bfloat16 lo = __float2bfloat16(f - __bfloat162float(hi));
        uint32_t o = (uint32_t)(n * 128 + 2 * k);
        o = o ^ ((o >> 3) & 0x70);
        *(__nv_bfloat16*)(base + OFF_BHI + o) = hi;
        *(__nv_bfloat16*)(base + OFF_BLO + o) = lo;
    }
    for (int idx = t; idx < 3 * NN; idx += 256) s_coord[idx] = coords[idx];
    if (t < LL) {
        s_preib[t] = g_preib[i * LL + t];
        s_w1z[t]   = We1[2 * LL * LL + t];
        s_be2[t]   = be2[t];
    }
    __syncthreads();

    // be2 per epilogue column (regs)
    float be2v[8][2];
    {
        const int cb = 2 * (lane & 3);
#pragma unroll
        for (int nt = 0; nt < 8; nt++) {
            be2v[nt][0] = s_be2[nt * 8 + cb];
            be2v[nt][1] = s_be2[nt * 8 + cb + 1];
        }
    }

    const float zx = s_coord[3 * i], zy = s_coord[3 * i + 1], zz = s_coord[3 * i + 2];

    // phase-1 lane mapping: row r1 = lane/2, k-half ks = (lane&1)*32
    const int r1  = lane >> 1;
    const int ks  = (lane & 1) * 32;
    const uint32_t xorS = (uint32_t)((r1 & 7) << 4);
    char* AH = base + OFF_A + w * 4096;       // hi tile; lo at +2048

    // ldmatrix A lane mapping
    const int rowA = (lane & 7) + ((lane >> 3) & 1) * 8;
    const uint32_t m16A = (uint32_t)((lane >> 4) * 16);
    const uint32_t xorA = (uint32_t)((rowA & 7) << 4);
    const uint32_t abHi = sb + OFF_A + (uint32_t)w * 4096u + (uint32_t)rowA * 128u;

    // ldmatrix B lane mapping (x4: covers n-pair x k-halves for one precision)
    const int brow = lane & 7;
    const int bg   = lane >> 3;                       // 0..3
    const uint32_t bns  = (uint32_t)(bg >> 1) * 1024u; // n within pair
    const uint32_t bks  = (uint32_t)(bg & 1) * 16u;    // k-half
    const uint32_t xorB = (uint32_t)(brow << 4);
    const uint32_t bHi  = sb + OFF_BHI + bns + (uint32_t)brow * 128u;
    const uint32_t bLo  = sb + OFF_BLO + bns + (uint32_t)brow * 128u;

    // epilogue mapping
    const int row0 = lane >> 2;

    float vpart = 0.0f;

    for (int tile = 0; tile < 8; tile++) {
        const int jbase = w * 128 + tile * 16;
        __syncwarp();
        // ---------------- phase 1: build A hi/lo ----------------
        {
            const int j = jbase + r1;
            float dx = zx - s_coord[3 * j];
            float dy = zy - s_coord[3 * j + 1];
            float dz = zz - s_coord[3 * j + 2];
            float d2 = dx * dx + dy * dy + dz * dz;
            const float4* pj = (const float4*)(g_prej + j * LL + ks);
#pragma unroll
            for (int p8 = 0; p8 < 4; p8++) {
                float4 u = pj[p8 * 2], v = pj[p8 * 2 + 1];
                const int k0 = ks + p8 * 8;
                float pv[8] = {u.x, u.y, u.z, u.w, v.x, v.y, v.z, v.w};
                uint4 HI, LO;
                uint32_t* hp = (uint32_t*)&HI;
                uint32_t* lp = (uint32_t*)&LO;
#pragma unroll
                for (int q = 0; q < 4; q++) {
                    float2 pr = *(const float2*)&s_preib[k0 + 2 * q];
                    float2 wz = *(const float2*)&s_w1z[k0 + 2 * q];
                    float h0 = htanh(fmaf(d2, wz.x, pr.x + pv[2 * q]));
                    float h1 = htanh(fmaf(d2, wz.y, pr.y + pv[2 * q + 1]));
                    __nv_bfloat162 hh = __floats2bfloat162_rn(h0, h1);
                    hp[q] = *reinterpret_cast<uint32_t*>(&hh);
                    float l0 = h0 - __bfloat162float(hh.x);
                    float l1 = h1 - __bfloat162float(hh.y);
                    lp[q] = pkbf2(l0, l1);
                }
                uint32_t o = (uint32_t)(r1 * 128) + (((uint32_t)(k0 * 2)) ^ xorS);
                *(uint4*)(AH + o)        = HI;
                *(uint4*)(AH + 2048 + o) = LO;
            }
        }
        __syncwarp();
        // ---------------- phase 2: MMAs ----------------
        uint32_t ahi[4][4], alo[4][4];
#pragma unroll
        for (int kk = 0; kk < 4; kk++) {
            uint32_t o = (m16A + (uint32_t)(kk * 32)) ^ xorA;
            ldsm4(ahi[kk], abHi + o);
            ldsm4(alo[kk], abHi + 2048u + o);
        }
        const bool mytile = (jbase <= i) && (i < jbase + 16);
        const int rowi = i - jbase;
#pragma unroll
        for (int ntp = 0; ntp < 4; ntp++) {
            const int n0 = 2 * ntp, n1 = n0 + 1;
            const uint32_t nOff = (uint32_t)(ntp * 2048);
            float c0[4] = {0.f, 0.f, 0.f, 0.f};
            float c1[4] = {0.f, 0.f, 0.f, 0.f};
#pragma unroll
            for (int kk = 0; kk < 4; kk++) {
                uint32_t col = ((uint32_t)(kk * 32) + bks) ^ xorB;
                uint32_t bh[4], bl[4];
                ldsm4(bh, bHi + nOff + col);
                ldsm4(bl, bLo + nOff + col);
                mma16816(c0, ahi[kk], bh);
                mma16816(c1, ahi[kk], bh + 2);
                mma16816(c0, alo[kk], bh);
                mma16816(c1, alo[kk], bh + 2);
                mma16816(c0, ahi[kk], bl);
                mma16816(c1, ahi[kk], bl + 2);
            }
            float acc0 = htanh(c0[0] + be2v[n0][0]) + htanh(c0[1] + be2v[n0][1])
                       + htanh(c1[0] + be2v[n1][0]) + htanh(c1[1] + be2v[n1][1]);
            float acc1 = htanh(c0[2] + be2v[n0][0]) + htanh(c0[3] + be2v[n0][1])
                       + htanh(c1[2] + be2v[n1][0]) + htanh(c1[3] + be2v[n1][1]);
            if (!(mytile && row0 == rowi))     vpart += acc0;
            if (!(mytile && row0 + 8 == rowi)) vpart += acc1;
        }
    }

    // reduce V over warp + block
#pragma unroll
    for (int o = 16; o > 0; o >>= 1)
        vpart += __shfl_down_sync(0xffffffffu, vpart, o);
    if (lane == 0) s_red[w] = vpart;
    __syncthreads();
    if (t == 0) {
        float v = 0.f;
#pragma unroll
        for (int q = 0; q < 8; q++) v += s_red[q];
        g_V[i] = v;
    }
}

// ---------------------------------------------------------------------------
// Kernel C1: hh = tanh(H@Wh1[:L] + V*Wh1[L] + bh1); newH = tanh(hh@Wh2 + bh2)
// ---------------------------------------------------------------------------
__global__ void head_kernel(const int* __restrict__ cats,
                            const float* __restrict__ LM,
                            const float* __restrict__ Wh1,
                            const float* __restrict__ bh1,
                            const float* __restrict__ Wh2,
                            const float* __restrict__ bh2) {
    __shared__ float Hs[LL];
    __shared__ float hhs[LL];
    int n = blockIdx.x, l = threadIdx.x;
    Hs[l] = LM[cats[n] * LL + l];
    __syncthreads();
    float V = g_V[n];
    float acc = fmaf(V, Wh1[LL * LL + l], bh1[l]);
#pragma unroll
    for (int k = 0; k < LL; k++)
        acc = fmaf(Hs[k], Wh1[k * LL + l], acc);
    hhs[l] = tanhf(acc);
    __syncthreads();
    float acc2 = bh2[l];
#pragma unroll
    for (int k = 0; k < LL; k++)
        acc2 = fmaf(hhs[k], Wh2[k * LL + l], acc2);
    g_newH[n * LL + l] = tanhf(acc2);
}

// ---------------------------------------------------------------------------
__global__ void final1_kernel() {
    __shared__ float s[256];
    int b = blockIdx.x, t = threadIdx.x;
    int l = t & 63, r = t >> 6;
    float acc = 0.f;
#pragma unroll
    for (int m = 0; m < 2; m++) {
        int n = b * 8 + r * 2 + m;
        acc += g_newH[n * LL + l];
    }
    s[t] = acc;
    __syncthreads();
    if (t < 64)
        g_part[b * LL + t] = s[t] + s[t + 64] + s[t + 128] + s[t + 192];
}

__global__ void final2_kernel(const float* __restrict__ Wo,
                              const float* __restrict__ bo,
                              float* __restrict__ out) {
    __shared__ float s_w[2];
    int t = threadIdx.x;          // 64 threads
    float h = 0.f;
#pragma unroll
    for (int q = 0; q < 128; q++)
        h += g_part[q * LL + t];
    float v = h * Wo[t];
#pragma unroll
    for (int o = 16; o > 0; o >>= 1)
        v += __shfl_down_sync(0xffffffffu, v, o);
    if ((t & 31) == 0) s_w[t >> 5] = v;
    __syncthreads();
    if (t == 0) out[0] = s_w[0] + s_w[1] + bo[0];
}

// ---------------------------------------------------------------------------
extern "C" void kernel_launch(void* const* d_in, const int* in_sizes, int n_in,
                              void* d_out, int out_size) {
    (void)in_sizes; (void)n_in; (void)out_size;
    const int*   cats   = (const int*)  d_in[0];
    const float* coords = (const float*)d_in[1];
    const float* LM     = (const float*)d_in[2];
    const float* We1    = (const float*)d_in[3];
    const float* be1    = (const float*)d_in[4];
    const float* We2    = (const float*)d_in[5];
    const float* be2    = (const float*)d_in[6];
    const float* Wh1    = (const float*)d_in[7];
    const float* bh1    = (const float*)d_in[8];
    const float* Wh2    = (const float*)d_in[9];
    const float* bh2    = (const float*)d_in[10];
    const float* Wo     = (const float*)d_in[11];
    const float* bo     = (const float*)d_in[12];

    cudaFuncSetAttribute(pair_kernel,
                         cudaFuncAttributeMaxDynamicSharedMemorySize, DYN_BYTES);

    prep_kernel  <<<NN, LL >>>(cats, LM, We1, be1);
    pair_kernel  <<<NN, 256, DYN_BYTES>>>(coords, We1, We2, be2);
    head_kernel  <<<NN, LL >>>(cats, LM, Wh1, bh1, Wh2, bh2);
    final1_kernel<<<128, 256>>>();
    final2_kernel<<<1,  64 >>>(Wo, bo, (float*)d_out);
}

// round 7
// speedup vs baseline: 2.3843x; 1.1088x over previous
#include <cuda_runtime.h>
#include <cuda_bf16.h>
#include <cstdint>

#define NN 1024
#define LL 64

// scratch (allocation-free rule: device globals)
__device__ __align__(16) float g_preib[NN * LL];   // pre_i + be1
__device__ __align__(16) float g_prej [NN * LL];   // pre_j
__device__ float g_V[NN];
__device__ __align__(16) float g_newH[NN * LL];
__device__ float g_part[128 * LL];

// HW tanh: 1 MUFU op
__device__ __forceinline__ float htanh(float x) {
    float y;
    asm("tanh.approx.f32 %0, %1;" : "=f"(y) : "f"(x));
    return y;
}

__device__ __forceinline__ uint32_t smem_u32(const void* p) {
    uint32_t a;
    asm("{ .reg .u64 t; cvta.to.shared.u64 t, %1; cvt.u32.u64 %0, t; }" : "=r"(a) : "l"(p));
    return a;
}
__device__ __forceinline__ void ldsm4(uint32_t* r, uint32_t addr) {
    asm volatile("ldmatrix.sync.aligned.m8n8.x4.shared.b16 {%0,%1,%2,%3}, [%4];"
                 : "=r"(r[0]), "=r"(r[1]), "=r"(r[2]), "=r"(r[3]) : "r"(addr));
}
__device__ __forceinline__ void mma16816(float* c, const uint32_t* a, const uint32_t* b) {
    asm volatile(
        "mma.sync.aligned.m16n8k16.row.col.f32.bf16.bf16.f32 "
        "{%0,%1,%2,%3},{%4,%5,%6,%7},{%8,%9},{%0,%1,%2,%3};"
        : "+f"(c[0]), "+f"(c[1]), "+f"(c[2]), "+f"(c[3])
        : "r"(a[0]), "r"(a[1]), "r"(a[2]), "r"(a[3]), "r"(b[0]), "r"(b[1]));
}

// dynamic smem layout (offsets from 1024-aligned base)
#define OFF_A      0u          // 8 warps x 2KB = 16KB (A tiles, bf16)
#define OFF_BHI    16384u      // 8KB (B bf16, [n][k] swizzled)
#define OFF_COORD  24576u      // 12KB
#define OFF_PREIB  36864u      // 256B
#define OFF_W1Z    37120u      // 256B
#define OFF_BE2    37376u      // 256B
#define DYN_BYTES  (37632u + 1024u)

// ---------------------------------------------------------------------------
// Kernel A: H = LM[cat]; preib = H @ We1[:L] + be1 ; prej = H @ We1[L:2L]
// ---------------------------------------------------------------------------
__global__ void prep_kernel(const int* __restrict__ cats,
                            const float* __restrict__ LM,
                            const float* __restrict__ We1,
                            const float* __restrict__ be1) {
    __shared__ float Hs[LL];
    int n = blockIdx.x, l = threadIdx.x;
    Hs[l] = LM[cats[n] * LL + l];
    __syncthreads();
    float ai = be1[l], aj = 0.0f;
#pragma unroll
    for (int k = 0; k < LL; k++) {
        float h = Hs[k];
        ai = fmaf(h, We1[k * LL + l], ai);
        aj = fmaf(h, We1[(LL + k) * LL + l], aj);
    }
    g_preib[n * LL + l] = ai;
    g_prej[n * LL + l] = aj;
}

// ---------------------------------------------------------------------------
// Kernel B: block = atom i, 8 warps, warp w owns j in [w*128, w*128+128),
// 8 tiles of 16 j-rows. Single bf16 mma (fp32 accum): C = A @ B.
// tanh via MUFU.TANH. Error headroom measured in R4/R5 covers bf16 quant.
// ---------------------------------------------------------------------------
__global__ __launch_bounds__(256, 3)
void pair_kernel(const float* __restrict__ coords,
                 const float* __restrict__ We1,
                 const float* __restrict__ We2,
                 const float* __restrict__ be2) {
    extern __shared__ __align__(16) char dyn_raw[];
    char* base = (char*)((((uintptr_t)dyn_raw) + 1023) & ~(uintptr_t)1023);
    const uint32_t sb = smem_u32(base);

    __shared__ float s_red[8];

    float* s_coord = (float*)(base + OFF_COORD);
    float* s_preib = (float*)(base + OFF_PREIB);
    float* s_w1z   = (float*)(base + OFF_W1Z);
    float* s_be2   = (float*)(base + OFF_BE2);

    const int i = blockIdx.x;
    const int t = threadIdx.x;
    const int w = t >> 5, lane = t & 31;

    // ---- B smem: [n][k] bf16, SW128 swizzled, from gmem ----
    for (int idx = t; idx < LL * LL; idx += 256) {
        int n = idx & 63, k = idx >> 6;          // n fastest -> coalesced
        float f = We2[k * LL + n];
        uint32_t o = (uint32_t)(n * 128 + 2 * k);
        o = o ^ ((o >> 3) & 0x70);
        *(__nv_bfloat16*)(base + OFF_BHI + o) = __float2bfloat16(f);
    }
    for (int idx = t; idx < 3 * NN; idx += 256) s_coord[idx] = coords[idx];
    if (t < LL) {
        s_preib[t] = g_preib[i * LL + t];
        s_w1z[t]   = We1[2 * LL * LL + t];
        s_be2[t]   = be2[t];
    }
    __syncthreads();

    // be2 per epilogue column (regs)
    float be2v[8][2];
    {
        const int cb = 2 * (lane & 3);
#pragma unroll
        for (int nt = 0; nt < 8; nt++) {
            be2v[nt][0] = s_be2[nt * 8 + cb];
            be2v[nt][1] = s_be2[nt * 8 + cb + 1];
        }
    }

    const float zx = s_coord[3 * i], zy = s_coord[3 * i + 1], zz = s_coord[3 * i + 2];

    // phase-1 lane mapping: row r1 = lane/2, k-half ks = (lane&1)*32
    const int r1 = lane >> 1;
    const int ks = (lane & 1) * 32;
    const uint32_t xorS = (uint32_t)((r1 & 7) << 4);
    char* AH = base + OFF_A + w * 2048;

    // ldmatrix A lane mapping
    const int rowA = (lane & 7) + ((lane >> 3) & 1) * 8;
    const uint32_t m16A = (uint32_t)((lane >> 4) * 16);
    const uint32_t xorA = (uint32_t)((rowA & 7) << 4);
    const uint32_t abHi = sb + OFF_A + (uint32_t)w * 2048u + (uint32_t)rowA * 128u;

    // ldmatrix B lane mapping (x4 covers n-pair x k-halves)
    const int brow = lane & 7;
    const int bg   = lane >> 3;
    const uint32_t bns  = (uint32_t)(bg >> 1) * 1024u;
    const uint32_t bks  = (uint32_t)(bg & 1) * 16u;
    const uint32_t xorB = (uint32_t)(brow << 4);
    const uint32_t bHi  = sb + OFF_BHI + bns + (uint32_t)brow * 128u;

    // epilogue mapping
    const int row0 = lane >> 2;

    float vpart = 0.0f;

    for (int tile = 0; tile < 8; tile++) {
        const int jbase = w * 128 + tile * 16;
        __syncwarp();
        // ---------------- phase 1: build A (bf16) ----------------
        {
            const int j = jbase + r1;
            float dx = zx - s_coord[3 * j];
            float dy = zy - s_coord[3 * j + 1];
            float dz = zz - s_coord[3 * j + 2];
            float d2 = dx * dx + dy * dy + dz * dz;
            const float4* pj = (const float4*)(g_prej + j * LL + ks);
#pragma unroll
            for (int p8 = 0; p8 < 4; p8++) {
                float4 u = pj[p8 * 2], v = pj[p8 * 2 + 1];
                const int k0 = ks + p8 * 8;
                float pv[8] = {u.x, u.y, u.z, u.w, v.x, v.y, v.z, v.w};
                uint4 HI;
                uint32_t* hp = (uint32_t*)&HI;
#pragma unroll
                for (int q = 0; q < 4; q++) {
                    float2 pr = *(const float2*)&s_preib[k0 + 2 * q];
                    float2 wz = *(const float2*)&s_w1z[k0 + 2 * q];
                    float h0 = htanh(fmaf(d2, wz.x, pr.x + pv[2 * q]));
                    float h1 = htanh(fmaf(d2, wz.y, pr.y + pv[2 * q + 1]));
                    __nv_bfloat162 hh = __floats2bfloat162_rn(h0, h1);
                    hp[q] = *reinterpret_cast<uint32_t*>(&hh);
                }
                uint32_t o = (uint32_t)(r1 * 128) + (((uint32_t)(k0 * 2)) ^ xorS);
                *(uint4*)(AH + o) = HI;
            }
        }
        __syncwarp();
        // ---------------- phase 2: MMAs ----------------
        uint32_t ahi[4][4];
#pragma unroll
        for (int kk = 0; kk < 4; kk++) {
            uint32_t o = (m16A + (uint32_t)(kk * 32)) ^ xorA;
            ldsm4(ahi[kk], abHi + o);
        }
        const bool mytile = (jbase <= i) && (i < jbase + 16);
        const int rowi = i - jbase;
#pragma unroll
        for (int ntp = 0; ntp < 4; ntp++) {
            const int n0 = 2 * ntp, nx = n0 + 1;
            const uint32_t nOff = (uint32_t)(ntp * 2048);
            float c0[4] = {0.f, 0.f, 0.f, 0.f};
            float c1[4] = {0.f, 0.f, 0.f, 0.f};
#pragma unroll
            for (int kk = 0; kk < 4; kk++) {
                uint32_t col = ((uint32_t)(kk * 32) + bks) ^ xorB;
                uint32_t bh[4];
                ldsm4(bh, bHi + nOff + col);
                mma16816(c0, ahi[kk], bh);
                mma16816(c1, ahi[kk], bh + 2);
            }
            float acc0 = htanh(c0[0] + be2v[n0][0]) + htanh(c0[1] + be2v[n0][1])
                       + htanh(c1[0] + be2v[nx][0]) + htanh(c1[1] + be2v[nx][1]);
            float acc1 = htanh(c0[2] + be2v[n0][0]) + htanh(c0[3] + be2v[n0][1])
                       + htanh(c1[2] + be2v[nx][0]) + htanh(c1[3] + be2v[nx][1]);
            if (!(mytile && row0 == rowi))     vpart += acc0;
            if (!(mytile && row0 + 8 == rowi)) vpart += acc1;
        }
    }

    // reduce V over warp + block
#pragma unroll
    for (int o = 16; o > 0; o >>= 1)
        vpart += __shfl_down_sync(0xffffffffu, vpart, o);
    if (lane == 0) s_red[w] = vpart;
    __syncthreads();
    if (t == 0) {
        float v = 0.f;
#pragma unroll
        for (int q = 0; q < 8; q++) v += s_red[q];
        g_V[i] = v;
    }
}

// ---------------------------------------------------------------------------
// Kernel C1: hh = tanh(H@Wh1[:L] + V*Wh1[L] + bh1); newH = tanh(hh@Wh2 + bh2)
// ---------------------------------------------------------------------------
__global__ void head_kernel(const int* __restrict__ cats,
                            const float* __restrict__ LM,
                            const float* __restrict__ Wh1,
                            const float* __restrict__ bh1,
                            const float* __restrict__ Wh2,
                            const float* __restrict__ bh2) {
    __shared__ float Hs[LL];
    __shared__ float hhs[LL];
    int n = blockIdx.x, l = threadIdx.x;
    Hs[l] = LM[cats[n] * LL + l];
    __syncthreads();
    float V = g_V[n];
    float acc = fmaf(V, Wh1[LL * LL + l], bh1[l]);
#pragma unroll
    for (int k = 0; k < LL; k++)
        acc = fmaf(Hs[k], Wh1[k * LL + l], acc);
    hhs[l] = tanhf(acc);
    __syncthreads();
    float acc2 = bh2[l];
#pragma unroll
    for (int k = 0; k < LL; k++)
        acc2 = fmaf(hhs[k], Wh2[k * LL + l], acc2);
    g_newH[n * LL + l] = tanhf(acc2);
}

// ---------------------------------------------------------------------------
__global__ void final1_kernel() {
    __shared__ float s[256];
    int b = blockIdx.x, t = threadIdx.x;
    int l = t & 63, r = t >> 6;
    float acc = 0.f;
#pragma unroll
    for (int m = 0; m < 2; m++) {
        int n = b * 8 + r * 2 + m;
        acc += g_newH[n * LL + l];
    }
    s[t] = acc;
    __syncthreads();
    if (t < 64)
        g_part[b * LL + t] = s[t] + s[t + 64] + s[t + 128] + s[t + 192];
}

__global__ void final2_kernel(const float* __restrict__ Wo,
                              const float* __restrict__ bo,
                              float* __restrict__ out) {
    __shared__ float s_w[2];
    int t = threadIdx.x;          // 64 threads
    float h = 0.f;
#pragma unroll
    for (int q = 0; q < 128; q++)
        h += g_part[q * LL + t];
    float v = h * Wo[t];
#pragma unroll
    for (int o = 16; o > 0; o >>= 1)
        v += __shfl_down_sync(0xffffffffu, v, o);
    if ((t & 31) == 0) s_w[t >> 5] = v;
    __syncthreads();
    if (t == 0) out[0] = s_w[0] + s_w[1] + bo[0];
}

// ---------------------------------------------------------------------------
extern "C" void kernel_launch(void* const* d_in, const int* in_sizes, int n_in,
                              void* d_out, int out_size) {
    (void)in_sizes; (void)n_in; (void)out_size;
    const int*   cats   = (const int*)  d_in[0];
    const float* coords = (const float*)d_in[1];
    const float* LM     = (const float*)d_in[2];
    const float* We1    = (const float*)d_in[3];
    const float* be1    = (const float*)d_in[4];
    const float* We2    = (const float*)d_in[5];
    const float* be2    = (const float*)d_in[6];
    const float* Wh1    = (const float*)d_in[7];
    const float* bh1    = (const float*)d_in[8];
    const float* Wh2    = (const float*)d_in[9];
    const float* bh2    = (const float*)d_in[10];
    const float* Wo     = (const float*)d_in[11];
    const float* bo     = (const float*)d_in[12];

    cudaFuncSetAttribute(pair_kernel,
                         cudaFuncAttributeMaxDynamicSharedMemorySize, DYN_BYTES);

    prep_kernel  <<<NN, LL >>>(cats, LM, We1, be1);
    pair_kernel  <<<NN, 256, DYN_BYTES>>>(coords, We1, We2, be2);
    head_kernel  <<<NN, LL >>>(cats, LM, Wh1, bh1, Wh2, bh2);
    final1_kernel<<<128, 256>>>();
    final2_kernel<<<1,  64 >>>(Wo, bo, (float*)d_out);
}

// round 8
// speedup vs baseline: 2.6338x; 1.1046x over previous
#include <cuda_runtime.h>
#include <cuda_bf16.h>
#include <cstdint>

#define NN 1024
#define LL 64

// scratch (allocation-free rule: device globals)
__device__ __align__(16) float g_preib[NN * LL];   // pre_i + be1
__device__ __align__(16) float g_prej [NN * LL];   // pre_j
__device__ float g_Vp[NN * 4];                     // per-quadrant V partials
__device__ __align__(16) float g_newH[NN * LL];
__device__ __align__(16) __nv_bfloat16 g_Bsw[LL * LL];  // We2^T bf16, SW128-swizzled

// HW tanh: 1 MUFU op
__device__ __forceinline__ float htanh(float x) {
    float y;
    asm("tanh.approx.f32 %0, %1;" : "=f"(y) : "f"(x));
    return y;
}

__device__ __forceinline__ uint32_t smem_u32(const void* p) {
    uint32_t a;
    asm("{ .reg .u64 t; cvta.to.shared.u64 t, %1; cvt.u32.u64 %0, t; }" : "=r"(a) : "l"(p));
    return a;
}
__device__ __forceinline__ void ldsm4(uint32_t* r, uint32_t addr) {
    asm volatile("ldmatrix.sync.aligned.m8n8.x4.shared.b16 {%0,%1,%2,%3}, [%4];"
                 : "=r"(r[0]), "=r"(r[1]), "=r"(r[2]), "=r"(r[3]) : "r"(addr));
}
__device__ __forceinline__ void mma16816(float* c, const uint32_t* a, const uint32_t* b) {
    asm volatile(
        "mma.sync.aligned.m16n8k16.row.col.f32.bf16.bf16.f32 "
        "{%0,%1,%2,%3},{%4,%5,%6,%7},{%8,%9},{%0,%1,%2,%3};"
        : "+f"(c[0]), "+f"(c[1]), "+f"(c[2]), "+f"(c[3])
        : "r"(a[0]), "r"(a[1]), "r"(a[2]), "r"(a[3]), "r"(b[0]), "r"(b[1]));
}
__device__ __forceinline__ void l2prefetch(const void* p) {
    asm volatile("prefetch.global.L2 [%0];" :: "l"(p));
}

// dynamic smem layout (offsets from 1024-aligned base)
#define OFF_A      0u          // 8 warps x 2KB = 16KB (A tiles, bf16)
#define OFF_B      16384u      // 8KB (B bf16, [n][k] swizzled)
#define OFF_COORD  24576u      // 3KB (256 j coords)
#define OFF_PREIB  27648u      // 256B
#define OFF_W1Z    27904u      // 256B
#define OFF_BE2    28160u      // 256B
#define DYN_BYTES  (28416u + 1024u)

// ---------------------------------------------------------------------------
// Kernel 0: H = LM[cat]; preib = H @ We1[:L] + be1 ; prej = H @ We1[L:2L]
// ---------------------------------------------------------------------------
__global__ void prep_kernel(const int* __restrict__ cats,
                            const float* __restrict__ LM,
                            const float* __restrict__ We1,
                            const float* __restrict__ be1) {
    __shared__ float Hs[LL];
    int n = blockIdx.x, l = threadIdx.x;
    Hs[l] = LM[cats[n] * LL + l];
    __syncthreads();
    float ai = be1[l], aj = 0.0f;
#pragma unroll
    for (int k = 0; k < LL; k++) {
        float h = Hs[k];
        ai = fmaf(h, We1[k * LL + l], ai);
        aj = fmaf(h, We1[(LL + k) * LL + l], aj);
    }
    g_preib[n * LL + l] = ai;
    g_prej[n * LL + l] = aj;
}

// ---------------------------------------------------------------------------
// Kernel 1: build swizzled bf16 B = We2^T once
// ---------------------------------------------------------------------------
__global__ void buildB_kernel(const float* __restrict__ We2) {
    int t = threadIdx.x;
    for (int idx = t; idx < LL * LL; idx += 256) {
        int n = idx & 63, k = idx >> 6;
        float f = We2[k * LL + n];
        uint32_t o = (uint32_t)(n * 128 + 2 * k);
        o = o ^ ((o >> 3) & 0x70);
        *(__nv_bfloat16*)((char*)g_Bsw + o) = __float2bfloat16(f);
    }
}

// ---------------------------------------------------------------------------
// Kernel 2/3: pair kernel, 2048 blocks per launch.
// block: i = bid>>1, quad = qbase + (bid&1); handles j in [quad*256, +256).
// 8 warps x 2 tiles of 16 j-rows. bf16 mma (fp32 accum) C = A @ B,
// epilogue tanh(C + be2) summed -> g_Vp[i*4+quad]. Diagonal j==i skipped.
// ---------------------------------------------------------------------------
__global__ __launch_bounds__(256, 3)
void pair_kernel(const float* __restrict__ coords,
                 const float* __restrict__ We1,
                 const float* __restrict__ be2,
                 int qbase) {
    extern __shared__ __align__(16) char dyn_raw[];
    char* base = (char*)((((uintptr_t)dyn_raw) + 1023) & ~(uintptr_t)1023);
    const uint32_t sb = smem_u32(base);

    __shared__ float s_red[8];

    float* s_coord = (float*)(base + OFF_COORD);
    float* s_preib = (float*)(base + OFF_PREIB);
    float* s_w1z   = (float*)(base + OFF_W1Z);
    float* s_be2   = (float*)(base + OFF_BE2);

    const int i    = blockIdx.x >> 1;
    const int quad = qbase + (blockIdx.x & 1);
    const int jq   = quad * 256;
    const int t = threadIdx.x;
    const int w = t >> 5, lane = t & 31;

    // ---- stage pre-swizzled B (8KB copy), coords slice, vectors ----
    {
        const uint4* src = (const uint4*)g_Bsw;
        uint4* dst = (uint4*)(base + OFF_B);
        dst[t]       = src[t];
        dst[t + 256] = src[t + 256];
    }
    for (int idx = t; idx < 768; idx += 256) s_coord[idx] = coords[jq * 3 + idx];
    if (t < LL) {
        s_preib[t] = g_preib[i * LL + t];
        s_w1z[t]   = We1[2 * LL * LL + t];
        s_be2[t]   = be2[t];
    }
    __syncthreads();

    // be2 per epilogue column (regs)
    float be2v[8][2];
    {
        const int cb = 2 * (lane & 3);
#pragma unroll
        for (int nt = 0; nt < 8; nt++) {
            be2v[nt][0] = s_be2[nt * 8 + cb];
            be2v[nt][1] = s_be2[nt * 8 + cb + 1];
        }
    }

    const float zx = coords[3 * i], zy = coords[3 * i + 1], zz = coords[3 * i + 2];

    // phase-1 lane mapping: row r1 = lane/2, k-half ks = (lane&1)*32
    const int r1 = lane >> 1;
    const int ks = (lane & 1) * 32;
    const uint32_t xorS = (uint32_t)((r1 & 7) << 4);
    char* AH = base + OFF_A + w * 2048;

    // ldmatrix A lane mapping
    const int rowA = (lane & 7) + ((lane >> 3) & 1) * 8;
    const uint32_t m16A = (uint32_t)((lane >> 4) * 16);
    const uint32_t xorA = (uint32_t)((rowA & 7) << 4);
    const uint32_t abA = sb + OFF_A + (uint32_t)w * 2048u + (uint32_t)rowA * 128u;

    // ldmatrix B lane mapping (x4 covers n-pair x k-halves)
    const int brow = lane & 7;
    const int bg   = lane >> 3;
    const uint32_t bns  = (uint32_t)(bg >> 1) * 1024u;
    const uint32_t bks  = (uint32_t)(bg & 1) * 16u;
    const uint32_t xorB = (uint32_t)(brow << 4);
    const uint32_t bB   = sb + OFF_B + bns + (uint32_t)brow * 128u;

    // epilogue mapping
    const int row0 = lane >> 2;

    float vpart = 0.0f;

    // prefetch second tile's prej rows into L2
    l2prefetch(g_prej + (jq + (w + 8) * 16 + r1) * LL + ks);

#pragma unroll
    for (int tt = 0; tt < 2; tt++) {
        const int tile = w + tt * 8;            // 0..15 within quadrant
        const int jloc = tile * 16;
        const int jbase = jq + jloc;
        __syncwarp();
        // ---------------- phase 1: build A (bf16) ----------------
        {
            const int jl = jloc + r1;
            float dx = zx - s_coord[3 * jl];
            float dy = zy - s_coord[3 * jl + 1];
            float dz = zz - s_coord[3 * jl + 2];
            float d2 = dx * dx + dy * dy + dz * dz;
            const float4* pj = (const float4*)(g_prej + (jq + jl) * LL + ks);
#pragma unroll
            for (int p8 = 0; p8 < 4; p8++) {
                float4 u = pj[p8 * 2], v = pj[p8 * 2 + 1];
                const int k0 = ks + p8 * 8;
                float pv[8] = {u.x, u.y, u.z, u.w, v.x, v.y, v.z, v.w};
                uint4 HI;
                uint32_t* hp = (uint32_t*)&HI;
#pragma unroll
                for (int q = 0; q < 4; q++) {
                    float2 pr = *(const float2*)&s_preib[k0 + 2 * q];
                    float2 wz = *(const float2*)&s_w1z[k0 + 2 * q];
                    float h0 = htanh(fmaf(d2, wz.x, pr.x + pv[2 * q]));
                    float h1 = htanh(fmaf(d2, wz.y, pr.y + pv[2 * q + 1]));
                    __nv_bfloat162 hh = __floats2bfloat162_rn(h0, h1);
                    hp[q] = *reinterpret_cast<uint32_t*>(&hh);
                }
                uint32_t o = (uint32_t)(r1 * 128) + (((uint32_t)(k0 * 2)) ^ xorS);
                *(uint4*)(AH + o) = HI;
            }
        }
        __syncwarp();
        // ---------------- phase 2: MMAs ----------------
        uint32_t ahi[4][4];
#pragma unroll
        for (int kk = 0; kk < 4; kk++) {
            uint32_t o = (m16A + (uint32_t)(kk * 32)) ^ xorA;
            ldsm4(ahi[kk], abA + o);
        }
        const bool mytile = (jbase <= i) && (i < jbase + 16);
        const int rowi = i - jbase;
#pragma unroll
        for (int ntp = 0; ntp < 4; ntp++) {
            const int n0 = 2 * ntp, nx = n0 + 1;
            const uint32_t nOff = (uint32_t)(ntp * 2048);
            float c0[4] = {0.f, 0.f, 0.f, 0.f};
            float c1[4] = {0.f, 0.f, 0.f, 0.f};
#pragma unroll
            for (int kk = 0; kk < 4; kk++) {
                uint32_t col = ((uint32_t)(kk * 32) + bks) ^ xorB;
                uint32_t bh[4];
                ldsm4(bh, bB + nOff + col);
                mma16816(c0, ahi[kk], bh);
                mma16816(c1, ahi[kk], bh + 2);
            }
            float acc0 = htanh(c0[0] + be2v[n0][0]) + htanh(c0[1] + be2v[n0][1])
                       + htanh(c1[0] + be2v[nx][0]) + htanh(c1[1] + be2v[nx][1]);
            float acc1 = htanh(c0[2] + be2v[n0][0]) + htanh(c0[3] + be2v[n0][1])
                       + htanh(c1[2] + be2v[nx][0]) + htanh(c1[3] + be2v[nx][1]);
            if (!(mytile && row0 == rowi))     vpart += acc0;
            if (!(mytile && row0 + 8 == rowi)) vpart += acc1;
        }
    }

    // reduce over warp + block -> Vp[i][quad]
#pragma unroll
    for (int o = 16; o > 0; o >>= 1)
        vpart += __shfl_down_sync(0xffffffffu, vpart, o);
    if (lane == 0) s_red[w] = vpart;
    __syncthreads();
    if (t == 0) {
        float v = 0.f;
#pragma unroll
        for (int q = 0; q < 8; q++) v += s_red[q];
        g_Vp[i * 4 + quad] = v;
    }
}

// ---------------------------------------------------------------------------
// Kernel 4: head. V = sum of 4 quadrant partials.
// ---------------------------------------------------------------------------
__global__ void head_kernel(const int* __restrict__ cats,
                            const float* __restrict__ LM,
                            const float* __restrict__ Wh1,
                            const float* __restrict__ bh1,
                            const float* __restrict__ Wh2,
                            const float* __restrict__ bh2) {
    __shared__ float Hs[LL];
    __shared__ float hhs[LL];
    int n = blockIdx.x, l = threadIdx.x;
    Hs[l] = LM[cats[n] * LL + l];
    __syncthreads();
    float V = (g_Vp[n * 4 + 0] + g_Vp[n * 4 + 1]) + (g_Vp[n * 4 + 2] + g_Vp[n * 4 + 3]);
    float acc = fmaf(V, Wh1[LL * LL + l], bh1[l]);
#pragma unroll
    for (int k = 0; k < LL; k++)
        acc = fmaf(Hs[k], Wh1[k * LL + l], acc);
    hhs[l] = tanhf(acc);
    __syncthreads();
    float acc2 = bh2[l];
#pragma unroll
    for (int k = 0; k < LL; k++)
        acc2 = fmaf(hhs[k], Wh2[k * LL + l], acc2);
    g_newH[n * LL + l] = tanhf(acc2);
}

// ---------------------------------------------------------------------------
// Kernel 5: final. Hsum = sum_n newH; out = Hsum @ Wo + bo. One 1024-thr block.
// ---------------------------------------------------------------------------
__global__ void final_kernel(const float* __restrict__ Wo,
                             const float* __restrict__ bo,
                             float* __restrict__ out) {
    __shared__ float s[1024];
    __shared__ float s_w[2];
    int t = threadIdx.x;
    int l = t & 63, r = t >> 6;           // r in 0..15
    float acc = 0.f;
#pragma unroll 8
    for (int m = 0; m < 64; m++)
        acc += g_newH[(r + 16 * m) * LL + l];
    s[t] = acc;
    __syncthreads();
    if (t < 64) {
        float h = 0.f;
#pragma unroll
        for (int q = 0; q < 16; q++) h += s[q * 64 + t];
        float v = h * Wo[t];
#pragma unroll
        for (int o = 16; o > 0; o >>= 1)
            v += __shfl_down_sync(0xffffffffu, v, o);
        if ((t & 31) == 0) s_w[t >> 5] = v;
    }
    __syncthreads();
    if (t == 0) out[0] = s_w[0] + s_w[1] + bo[0];
}

// ---------------------------------------------------------------------------
extern "C" void kernel_launch(void* const* d_in, const int* in_sizes, int n_in,
                              void* d_out, int out_size) {
    (void)in_sizes; (void)n_in; (void)out_size;
    const int*   cats   = (const int*)  d_in[0];
    const float* coords = (const float*)d_in[1];
    const float* LM     = (const float*)d_in[2];
    const float* We1    = (const float*)d_in[3];
    const float* be1    = (const float*)d_in[4];
    const float* We2    = (const float*)d_in[5];
    const float* be2    = (const float*)d_in[6];
    const float* Wh1    = (const float*)d_in[7];
    const float* bh1    = (const float*)d_in[8];
    const float* Wh2    = (const float*)d_in[9];
    const float* bh2    = (const float*)d_in[10];
    const float* Wo     = (const float*)d_in[11];
    const float* bo     = (const float*)d_in[12];

    cudaFuncSetAttribute(pair_kernel,
                         cudaFuncAttributeMaxDynamicSharedMemorySize, DYN_BYTES);

    prep_kernel  <<<NN, LL >>>(cats, LM, We1, be1);
    buildB_kernel<<<1, 256>>>(We2);
    pair_kernel  <<<2048, 256, DYN_BYTES>>>(coords, We1, be2, 0);
    pair_kernel  <<<2048, 256, DYN_BYTES>>>(coords, We1, be2, 2);
    head_kernel  <<<NN, LL >>>(cats, LM, Wh1, bh1, Wh2, bh2);
    final_kernel <<<1, 1024>>>(Wo, bo, (float*)d_out);
}

// round 9
// speedup vs baseline: 2.7388x; 1.0399x over previous
#include <cuda_runtime.h>
#include <cuda_bf16.h>
#include <cstdint>

#define NN 1024
#define LL 64

// scratch (allocation-free rule: device globals)
__device__ __align__(16) float g_preib[NN * LL];   // pre_i + be1
__device__ __align__(16) float g_prej [NN * LL];   // pre_j
__device__ float g_Vp[NN * 4];                     // per-quadrant V partials
__device__ __align__(16) float g_newH[NN * LL];
__device__ __align__(16) __nv_bfloat16 g_Bsw[LL * LL];  // We2^T bf16, SW128-swizzled

// HW tanh: 1 MUFU op
__device__ __forceinline__ float htanh(float x) {
    float y;
    asm("tanh.approx.f32 %0, %1;" : "=f"(y) : "f"(x));
    return y;
}

__device__ __forceinline__ uint32_t smem_u32(const void* p) {
    uint32_t a;
    asm("{ .reg .u64 t; cvta.to.shared.u64 t, %1; cvt.u32.u64 %0, t; }" : "=r"(a) : "l"(p));
    return a;
}
__device__ __forceinline__ void ldsm4(uint32_t* r, uint32_t addr) {
    asm volatile("ldmatrix.sync.aligned.m8n8.x4.shared.b16 {%0,%1,%2,%3}, [%4];"
                 : "=r"(r[0]), "=r"(r[1]), "=r"(r[2]), "=r"(r[3]) : "r"(addr));
}
__device__ __forceinline__ void mma16816(float* c, const uint32_t* a, const uint32_t* b) {
    asm volatile(
        "mma.sync.aligned.m16n8k16.row.col.f32.bf16.bf16.f32 "
        "{%0,%1,%2,%3},{%4,%5,%6,%7},{%8,%9},{%0,%1,%2,%3};"
        : "+f"(c[0]), "+f"(c[1]), "+f"(c[2]), "+f"(c[3])
        : "r"(a[0]), "r"(a[1]), "r"(a[2]), "r"(a[3]), "r"(b[0]), "r"(b[1]));
}
__device__ __forceinline__ void l2prefetch(const void* p) {
    asm volatile("prefetch.global.L2 [%0];" :: "l"(p));
}

// dynamic smem layout (offsets from 1024-aligned base)
#define OFF_A      0u          // 8 warps x 2KB = 16KB (A tiles, bf16)
#define OFF_B      16384u      // 8KB (B bf16, [n][k] swizzled)
#define OFF_COORD  24576u      // 3KB (256 j coords)
#define OFF_PW     27648u      // 512B (interleaved preib/w1z)
#define OFF_BE2    28160u      // 256B
#define DYN_BYTES  (28416u + 1024u)

// ---------------------------------------------------------------------------
// Kernel 0: H = LM[cat]; preib = H @ We1[:L] + be1 ; prej = H @ We1[L:2L]
// ---------------------------------------------------------------------------
__global__ void prep_kernel(const int* __restrict__ cats,
                            const float* __restrict__ LM,
                            const float* __restrict__ We1,
                            const float* __restrict__ be1) {
    __shared__ float Hs[LL];
    int n = blockIdx.x, l = threadIdx.x;
    Hs[l] = LM[cats[n] * LL + l];
    __syncthreads();
    float ai = be1[l], aj = 0.0f;
#pragma unroll
    for (int k = 0; k < LL; k++) {
        float h = Hs[k];
        ai = fmaf(h, We1[k * LL + l], ai);
        aj = fmaf(h, We1[(LL + k) * LL + l], aj);
    }
    g_preib[n * LL + l] = ai;
    g_prej[n * LL + l] = aj;
}

// ---------------------------------------------------------------------------
// Kernel 1: build swizzled bf16 B = We2^T once
// ---------------------------------------------------------------------------
__global__ void buildB_kernel(const float* __restrict__ We2) {
    int t = threadIdx.x;
    for (int idx = t; idx < LL * LL; idx += 256) {
        int n = idx & 63, k = idx >> 6;
        float f = We2[k * LL + n];
        uint32_t o = (uint32_t)(n * 128 + 2 * k);
        o = o ^ ((o >> 3) & 0x70);
        *(__nv_bfloat16*)((char*)g_Bsw + o) = __float2bfloat16(f);
    }
}

// ---------------------------------------------------------------------------
// Kernel 2/3: pair kernel, 2048 blocks per launch.
// block: i = bid>>1, quad = qbase + (bid&1); handles j in [quad*256, +256).
// 8 warps x 2 tiles of 16 j-rows. bf16 mma (fp32 accum) C = A @ B.
// B fragments hoisted into 64 registers (loaded once per block) — removes the
// dominant L1TEX traffic measured in R8 (76% L1, B-ldsm = 57% of wavefronts).
// ---------------------------------------------------------------------------
__global__ __launch_bounds__(256, 2)
void pair_kernel(const float* __restrict__ coords,
                 const float* __restrict__ We1,
                 const float* __restrict__ be2,
                 int qbase) {
    extern __shared__ __align__(16) char dyn_raw[];
    char* base = (char*)((((uintptr_t)dyn_raw) + 1023) & ~(uintptr_t)1023);
    const uint32_t sb = smem_u32(base);

    __shared__ float s_red[8];

    float* s_coord = (float*)(base + OFF_COORD);
    float* s_pw    = (float*)(base + OFF_PW);    // [2k]=preib, [2k+1]=w1z
    float* s_be2   = (float*)(base + OFF_BE2);

    const int i    = blockIdx.x >> 1;
    const int quad = qbase + (blockIdx.x & 1);
    const int jq   = quad * 256;
    const int t = threadIdx.x;
    const int w = t >> 5, lane = t & 31;

    // ---- stage pre-swizzled B (8KB copy), coords slice, vectors ----
    {
        const uint4* src = (const uint4*)g_Bsw;
        uint4* dst = (uint4*)(base + OFF_B);
        dst[t]       = src[t];
        dst[t + 256] = src[t + 256];
    }
    for (int idx = t; idx < 768; idx += 256) s_coord[idx] = coords[jq * 3 + idx];
    if (t < LL) {
        s_pw[2 * t]     = g_preib[i * LL + t];
        s_pw[2 * t + 1] = We1[2 * LL * LL + t];
        s_be2[t]        = be2[t];
    }
    __syncthreads();

    const float zx = coords[3 * i], zy = coords[3 * i + 1], zz = coords[3 * i + 2];

    // phase-1 lane mapping: row r1 = lane/2, k-half ks = (lane&1)*32
    const int r1 = lane >> 1;
    const int ks = (lane & 1) * 32;
    const uint32_t xorS = (uint32_t)((r1 & 7) << 4);
    char* AH = base + OFF_A + w * 2048;

    // ldmatrix A lane mapping
    const int rowA = (lane & 7) + ((lane >> 3) & 1) * 8;
    const uint32_t m16A = (uint32_t)((lane >> 4) * 16);
    const uint32_t xorA = (uint32_t)((rowA & 7) << 4);
    const uint32_t abA = sb + OFF_A + (uint32_t)w * 2048u + (uint32_t)rowA * 128u;

    // ldmatrix B lane mapping (x4 covers n-pair x k-halves)
    const int brow = lane & 7;
    const int bg   = lane >> 3;
    const uint32_t bns  = (uint32_t)(bg >> 1) * 1024u;
    const uint32_t bks  = (uint32_t)(bg & 1) * 16u;
    const uint32_t xorB = (uint32_t)(brow << 4);
    const uint32_t bB   = sb + OFF_B + bns + (uint32_t)brow * 128u;

    // ---- hoist ALL B fragments into registers (once per block) ----
    uint32_t breg[4][4][4];
#pragma unroll
    for (int ntp = 0; ntp < 4; ntp++)
#pragma unroll
        for (int kk = 0; kk < 4; kk++) {
            uint32_t col = ((uint32_t)(kk * 32) + bks) ^ xorB;
            ldsm4(breg[ntp][kk], bB + (uint32_t)(ntp * 2048) + col);
        }

    // epilogue mapping
    const int row0 = lane >> 2;
    const int cb = 2 * (lane & 3);

    float vpart = 0.0f;

    // prefetch second tile's prej rows into L2
    l2prefetch(g_prej + (jq + (w + 8) * 16 + r1) * LL + ks);

#pragma unroll
    for (int tt = 0; tt < 2; tt++) {
        const int tile = w + tt * 8;            // 0..15 within quadrant
        const int jloc = tile * 16;
        const int jbase = jq + jloc;
        __syncwarp();
        // ---------------- phase 1: build A (bf16) ----------------
        {
            const int jl = jloc + r1;
            float dx = zx - s_coord[3 * jl];
            float dy = zy - s_coord[3 * jl + 1];
            float dz = zz - s_coord[3 * jl + 2];
            float d2 = dx * dx + dy * dy + dz * dz;
            const float4* pj = (const float4*)(g_prej + (jq + jl) * LL + ks);
#pragma unroll
            for (int p8 = 0; p8 < 4; p8++) {
                float4 u = pj[p8 * 2], v = pj[p8 * 2 + 1];
                const int k0 = ks + p8 * 8;
                float pv[8] = {u.x, u.y, u.z, u.w, v.x, v.y, v.z, v.w};
                uint4 HI;
                uint32_t* hp = (uint32_t*)&HI;
#pragma unroll
                for (int q = 0; q < 4; q++) {
                    float4 pw = *(const float4*)&s_pw[2 * (k0 + 2 * q)];
                    float h0 = htanh(fmaf(d2, pw.y, pw.x + pv[2 * q]));
                    float h1 = htanh(fmaf(d2, pw.w, pw.z + pv[2 * q + 1]));
                    __nv_bfloat162 hh = __floats2bfloat162_rn(h0, h1);
                    hp[q] = *reinterpret_cast<uint32_t*>(&hh);
                }
                uint32_t o = (uint32_t)(r1 * 128) + (((uint32_t)(k0 * 2)) ^ xorS);
                *(uint4*)(AH + o) = HI;
            }
        }
        __syncwarp();
        // ---------------- phase 2: MMAs (B from registers) ----------------
        uint32_t ahi[4][4];
#pragma unroll
        for (int kk = 0; kk < 4; kk++) {
            uint32_t o = (m16A + (uint32_t)(kk * 32)) ^ xorA;
            ldsm4(ahi[kk], abA + o);
        }
        const bool mytile = (jbase <= i) && (i < jbase + 16);
        const int rowi = i - jbase;
#pragma unroll
        for (int ntp = 0; ntp < 4; ntp++) {
            const int n0 = 2 * ntp, nx = n0 + 1;
            float c0[4] = {0.f, 0.f, 0.f, 0.f};
            float c1[4] = {0.f, 0.f, 0.f, 0.f};
#pragma unroll
            for (int kk = 0; kk < 4; kk++) {
                mma16816(c0, ahi[kk], breg[ntp][kk]);
                mma16816(c1, ahi[kk], breg[ntp][kk] + 2);
            }
            float b00 = s_be2[n0 * 8 + cb], b01 = s_be2[n0 * 8 + cb + 1];
            float b10 = s_be2[nx * 8 + cb], b11 = s_be2[nx * 8 + cb + 1];
            float acc0 = htanh(c0[0] + b00) + htanh(c0[1] + b01)
                       + htanh(c1[0] + b10) + htanh(c1[1] + b11);
            float acc1 = htanh(c0[2] + b00) + htanh(c0[3] + b01)
                       + htanh(c1[2] + b10) + htanh(c1[3] + b11);
            if (!(mytile && row0 == rowi))     vpart += acc0;
            if (!(mytile && row0 + 8 == rowi)) vpart += acc1;
        }
    }

    // reduce over warp + block -> Vp[i][quad]
#pragma unroll
    for (int o = 16; o > 0; o >>= 1)
        vpart += __shfl_down_sync(0xffffffffu, vpart, o);
    if (lane == 0) s_red[w] = vpart;
    __syncthreads();
    if (t == 0) {
        float v = 0.f;
#pragma unroll
        for (int q = 0; q < 8; q++) v += s_red[q];
        g_Vp[i * 4 + quad] = v;
    }
}

// ---------------------------------------------------------------------------
// Kernel 4: head. V = sum of 4 quadrant partials.
// ---------------------------------------------------------------------------
__global__ void head_kernel(const int* __restrict__ cats,
                            const float* __restrict__ LM,
                            const float* __restrict__ Wh1,
                            const float* __restrict__ bh1,
                            const float* __restrict__ Wh2,
                            const float* __restrict__ bh2) {
    __shared__ float Hs[LL];
    __shared__ float hhs[LL];
    int n = blockIdx.x, l = threadIdx.x;
    Hs[l] = LM[cats[n] * LL + l];
    __syncthreads();
    float V = (g_Vp[n * 4 + 0] + g_Vp[n * 4 + 1]) + (g_Vp[n * 4 + 2] + g_Vp[n * 4 + 3]);
    float acc = fmaf(V, Wh1[LL * LL + l], bh1[l]);
#pragma unroll
    for (int k = 0; k < LL; k++)
        acc = fmaf(Hs[k], Wh1[k * LL + l], acc);
    hhs[l] = tanhf(acc);
    __syncthreads();
    float acc2 = bh2[l];
#pragma unroll
    for (int k = 0; k < LL; k++)
        acc2 = fmaf(hhs[k], Wh2[k * LL + l], acc2);
    g_newH[n * LL + l] = tanhf(acc2);
}

// ---------------------------------------------------------------------------
// Kernel 5: final. Hsum = sum_n newH; out = Hsum @ Wo + bo. One 1024-thr block.
// ---------------------------------------------------------------------------
__global__ void final_kernel(const float* __restrict__ Wo,
                             const float* __restrict__ bo,
                             float* __restrict__ out) {
    __shared__ float s[1024];
    __shared__ float s_w[2];
    int t = threadIdx.x;
    int l = t & 63, r = t >> 6;           // r in 0..15
    float acc = 0.f;
#pragma unroll 8
    for (int m = 0; m < 64; m++)
        acc += g_newH[(r + 16 * m) * LL + l];
    s[t] = acc;
    __syncthreads();
    if (t < 64) {
        float h = 0.f;
#pragma unroll
        for (int q = 0; q < 16; q++) h += s[q * 64 + t];
        float v = h * Wo[t];
#pragma unroll
        for (int o = 16; o > 0; o >>= 1)
            v += __shfl_down_sync(0xffffffffu, v, o);
        if ((t & 31) == 0) s_w[t >> 5] = v;
    }
    __syncthreads();
    if (t == 0) out[0] = s_w[0] + s_w[1] + bo[0];
}

// ---------------------------------------------------------------------------
extern "C" void kernel_launch(void* const* d_in, const int* in_sizes, int n_in,
                              void* d_out, int out_size) {
    (void)in_sizes; (void)n_in; (void)out_size;
    const int*   cats   = (const int*)  d_in[0];
    const float* coords = (const float*)d_in[1];
    const float* LM     = (const float*)d_in[2];
    const float* We1    = (const float*)d_in[3];
    const float* be1    = (const float*)d_in[4];
    const float* We2    = (const float*)d_in[5];
    const float* be2    = (const float*)d_in[6];
    const float* Wh1    = (const float*)d_in[7];
    const float* bh1    = (const float*)d_in[8];
    const float* Wh2    = (const float*)d_in[9];
    const float* bh2    = (const float*)d_in[10];
    const float* Wo     = (const float*)d_in[11];
    const float* bo     = (const float*)d_in[12];

    cudaFuncSetAttribute(pair_kernel,
                         cudaFuncAttributeMaxDynamicSharedMemorySize, DYN_BYTES);

    prep_kernel  <<<NN, LL >>>(cats, LM, We1, be1);
    buildB_kernel<<<1, 256>>>(We2);
    pair_kernel  <<<2048, 256, DYN_BYTES>>>(coords, We1, be2, 0);
    pair_kernel  <<<2048, 256, DYN_BYTES>>>(coords, We1, be2, 2);
    head_kernel  <<<NN, LL >>>(cats, LM, Wh1, bh1, Wh2, bh2);
    final_kernel <<<1, 1024>>>(Wo, bo, (float*)d_out);
}

// round 10
// speedup vs baseline: 4.9015x; 1.7897x over previous
#include <cuda_runtime.h>
#include <cuda_bf16.h>
#include <cstdint>

#define NN 1024
#define LL 64

// scratch (allocation-free rule: device globals)
__device__ __align__(16) float g_preib[NN * LL];   // pre_i + be1
__device__ __align__(16) float g_prej [NN * LL];   // pre_j
__device__ float g_Vp[NN * 4];                     // per-quadrant V partials
__device__ __align__(16) float g_newH[NN * LL];
__device__ __align__(16) __nv_bfloat16 g_Bsw[LL * LL];  // We2^T bf16, SW128-swizzled

// HW tanh: 1 MUFU op
__device__ __forceinline__ float htanh(float x) {
    float y;
    asm("tanh.approx.f32 %0, %1;" : "=f"(y) : "f"(x));
    return y;
}

__device__ __forceinline__ uint32_t smem_u32(const void* p) {
    uint32_t a;
    asm("{ .reg .u64 t; cvta.to.shared.u64 t, %1; cvt.u32.u64 %0, t; }" : "=r"(a) : "l"(p));
    return a;
}
__device__ __forceinline__ void ldsm4(uint32_t* r, uint32_t addr) {
    asm volatile("ldmatrix.sync.aligned.m8n8.x4.shared.b16 {%0,%1,%2,%3}, [%4];"
                 : "=r"(r[0]), "=r"(r[1]), "=r"(r[2]), "=r"(r[3]) : "r"(addr));
}
__device__ __forceinline__ void mma16816(float* c, const uint32_t* a, const uint32_t* b) {
    asm volatile(
        "mma.sync.aligned.m16n8k16.row.col.f32.bf16.bf16.f32 "
        "{%0,%1,%2,%3},{%4,%5,%6,%7},{%8,%9},{%0,%1,%2,%3};"
        : "+f"(c[0]), "+f"(c[1]), "+f"(c[2]), "+f"(c[3])
        : "r"(a[0]), "r"(a[1]), "r"(a[2]), "r"(a[3]), "r"(b[0]), "r"(b[1]));
}
__device__ __forceinline__ uint32_t pkbf2(float a, float b) {
    __nv_bfloat162 h = __floats2bfloat162_rn(a, b);
    return *reinterpret_cast<uint32_t*>(&h);
}

// dynamic smem layout (offsets from 1024-aligned base)
#define OFF_B      0u          // 8KB (B bf16, [n][k] swizzled)
#define OFF_D2     8192u       // 1KB (d2 for 256 j's vs this block's i)
#define OFF_PW     9216u       // 512B (interleaved preib/w1z)
#define OFF_BE2    9728u       // 256B
#define DYN_BYTES  (9984u + 1024u)

// ---------------------------------------------------------------------------
// Kernel 0: H = LM[cat]; preib = H @ We1[:L] + be1 ; prej = H @ We1[L:2L]
// ---------------------------------------------------------------------------
__global__ void prep_kernel(const int* __restrict__ cats,
                            const float* __restrict__ LM,
                            const float* __restrict__ We1,
                            const float* __restrict__ be1) {
    __shared__ float Hs[LL];
    int n = blockIdx.x, l = threadIdx.x;
    Hs[l] = LM[cats[n] * LL + l];
    __syncthreads();
    float ai = be1[l], aj = 0.0f;
#pragma unroll
    for (int k = 0; k < LL; k++) {
        float h = Hs[k];
        ai = fmaf(h, We1[k * LL + l], ai);
        aj = fmaf(h, We1[(LL + k) * LL + l], aj);
    }
    g_preib[n * LL + l] = ai;
    g_prej[n * LL + l] = aj;
}

// ---------------------------------------------------------------------------
// Kernel 1: build swizzled bf16 B = We2^T once
// ---------------------------------------------------------------------------
__global__ void buildB_kernel(const float* __restrict__ We2) {
    int t = threadIdx.x;
    for (int idx = t; idx < LL * LL; idx += 256) {
        int n = idx & 63, k = idx >> 6;
        float f = We2[k * LL + n];
        uint32_t o = (uint32_t)(n * 128 + 2 * k);
        o = o ^ ((o >> 3) & 0x70);
        *(__nv_bfloat16*)((char*)g_Bsw + o) = __float2bfloat16(f);
    }
}

// ---------------------------------------------------------------------------
// Kernel 2/3: pair kernel, 2048 blocks per launch.
// block: i = bid>>1, quad = qbase + (bid&1); handles j in [quad*256, +256).
// 8 warps x 2 tiles of 16 j-rows. bf16 mma (fp32 accum) C = A @ B.
// A fragments are computed DIRECTLY in mma lane layout (no smem round-trip,
// no syncwarp): lane owns rows {l/4, l/4+8} x cols {(l%4)*2+{0,1}+{0,8}+16kk}.
// B fragments hoisted to registers once per block. d2 precomputed per block.
// ---------------------------------------------------------------------------
__global__ __launch_bounds__(256, 2)
void pair_kernel(const float* __restrict__ coords,
                 const float* __restrict__ We1,
                 const float* __restrict__ be2,
                 int qbase) {
    extern __shared__ __align__(16) char dyn_raw[];
    char* base = (char*)((((uintptr_t)dyn_raw) + 1023) & ~(uintptr_t)1023);
    const uint32_t sb = smem_u32(base);

    __shared__ float s_red[8];

    float* s_d2  = (float*)(base + OFF_D2);
    float* s_pw  = (float*)(base + OFF_PW);    // [2k]=preib, [2k+1]=w1z
    float* s_be2 = (float*)(base + OFF_BE2);

    const int i    = blockIdx.x >> 1;
    const int quad = qbase + (blockIdx.x & 1);
    const int jq   = quad * 256;
    const int t = threadIdx.x;
    const int w = t >> 5, lane = t & 31;

    // ---- stage pre-swizzled B (8KB copy), d2, vectors ----
    {
        const uint4* src = (const uint4*)g_Bsw;
        uint4* dst = (uint4*)(base + OFF_B);
        dst[t]       = src[t];
        dst[t + 256] = src[t + 256];
    }
    {
        const float zx = coords[3 * i], zy = coords[3 * i + 1], zz = coords[3 * i + 2];
        int j = jq + t;
        float dx = zx - coords[3 * j];
        float dy = zy - coords[3 * j + 1];
        float dz = zz - coords[3 * j + 2];
        s_d2[t] = dx * dx + dy * dy + dz * dz;
    }
    if (t < LL) {
        s_pw[2 * t]     = g_preib[i * LL + t];
        s_pw[2 * t + 1] = We1[2 * LL * LL + t];
        s_be2[t]        = be2[t];
    }
    __syncthreads();

    // ldmatrix B lane mapping (x4 covers n-pair x k-halves)
    const int brow = lane & 7;
    const int bg   = lane >> 3;
    const uint32_t bns  = (uint32_t)(bg >> 1) * 1024u;
    const uint32_t bks  = (uint32_t)(bg & 1) * 16u;
    const uint32_t xorB = (uint32_t)(brow << 4);
    const uint32_t bB   = sb + OFF_B + bns + (uint32_t)brow * 128u;

    // ---- hoist ALL B fragments into registers (once per block) ----
    uint32_t breg[4][4][4];
#pragma unroll
    for (int ntp = 0; ntp < 4; ntp++)
#pragma unroll
        for (int kk = 0; kk < 4; kk++) {
            uint32_t col = ((uint32_t)(kk * 32) + bks) ^ xorB;
            ldsm4(breg[ntp][kk], bB + (uint32_t)(ntp * 2048) + col);
        }

    // fragment lane mapping
    const int rquad = lane >> 2;           // row within tile (and +8)
    const int cpair = (lane & 3) * 2;      // col pair base
    const int cb = cpair;                  // epilogue be2 col base

    float vpart = 0.0f;

#pragma unroll
    for (int tt = 0; tt < 2; tt++) {
        const int tile = w + tt * 8;            // 0..15 within quadrant
        const int jloc = tile * 16;
        const int jbase = jq + jloc;

        // ---------------- phase 1: A fragments directly ----------------
        const float d2a = s_d2[jloc + rquad];
        const float d2b = s_d2[jloc + rquad + 8];
        const float* pra = g_prej + (jbase + rquad) * LL;
        const float* prb = pra + 8 * LL;

        uint32_t ahi[4][4];
#pragma unroll
        for (int kk = 0; kk < 4; kk++) {
            const int c = cpair + 16 * kk;
            float4 pw0 = *(const float4*)&s_pw[2 * c];
            float4 pw1 = *(const float4*)&s_pw[2 * (c + 8)];
            float2 pA0 = *(const float2*)(pra + c);
            float2 pB0 = *(const float2*)(prb + c);
            float2 pA1 = *(const float2*)(pra + c + 8);
            float2 pB1 = *(const float2*)(prb + c + 8);
            ahi[kk][0] = pkbf2(htanh(fmaf(d2a, pw0.y, pw0.x + pA0.x)),
                               htanh(fmaf(d2a, pw0.w, pw0.z + pA0.y)));
            ahi[kk][1] = pkbf2(htanh(fmaf(d2b, pw0.y, pw0.x + pB0.x)),
                               htanh(fmaf(d2b, pw0.w, pw0.z + pB0.y)));
            ahi[kk][2] = pkbf2(htanh(fmaf(d2a, pw1.y, pw1.x + pA1.x)),
                               htanh(fmaf(d2a, pw1.w, pw1.z + pA1.y)));
            ahi[kk][3] = pkbf2(htanh(fmaf(d2b, pw1.y, pw1.x + pB1.x)),
                               htanh(fmaf(d2b, pw1.w, pw1.z + pB1.y)));
        }

        // ---------------- phase 2: MMAs (A and B from registers) --------
        const bool mytile = (jbase <= i) && (i < jbase + 16);
        const int rowi = i - jbase;
#pragma unroll
        for (int ntp = 0; ntp < 4; ntp++) {
            const int n0 = 2 * ntp, nx = n0 + 1;
            float c0[4] = {0.f, 0.f, 0.f, 0.f};
            float c1[4] = {0.f, 0.f, 0.f, 0.f};
#pragma unroll
            for (int kk = 0; kk < 4; kk++) {
                mma16816(c0, ahi[kk], breg[ntp][kk]);
                mma16816(c1, ahi[kk], breg[ntp][kk] + 2);
            }
            float b00 = s_be2[n0 * 8 + cb], b01 = s_be2[n0 * 8 + cb + 1];
            float b10 = s_be2[nx * 8 + cb], b11 = s_be2[nx * 8 + cb + 1];
            float acc0 = htanh(c0[0] + b00) + htanh(c0[1] + b01)
                       + htanh(c1[0] + b10) + htanh(c1[1] + b11);
            float acc1 = htanh(c0[2] + b00) + htanh(c0[3] + b01)
                       + htanh(c1[2] + b10) + htanh(c1[3] + b11);
            if (!(mytile && rquad == rowi))     vpart += acc0;
            if (!(mytile && rquad + 8 == rowi)) vpart += acc1;
        }
    }

    // reduce over warp + block -> Vp[i][quad]
#pragma unroll
    for (int o = 16; o > 0; o >>= 1)
        vpart += __shfl_down_sync(0xffffffffu, vpart, o);
    if (lane == 0) s_red[w] = vpart;
    __syncthreads();
    if (t == 0) {
        float v = 0.f;
#pragma unroll
        for (int q = 0; q < 8; q++) v += s_red[q];
        g_Vp[i * 4 + quad] = v;
    }
}

// ---------------------------------------------------------------------------
// Kernel 4: head. V = sum of 4 quadrant partials.
// ---------------------------------------------------------------------------
__global__ void head_kernel(const int* __restrict__ cats,
                            const float* __restrict__ LM,
                            const float* __restrict__ Wh1,
                            const float* __restrict__ bh1,
                            const float* __restrict__ Wh2,
                            const float* __restrict__ bh2) {
    __shared__ float Hs[LL];
    __shared__ float hhs[LL];
    int n = blockIdx.x, l = threadIdx.x;
    Hs[l] = LM[cats[n] * LL + l];
    __syncthreads();
    float V = (g_Vp[n * 4 + 0] + g_Vp[n * 4 + 1]) + (g_Vp[n * 4 + 2] + g_Vp[n * 4 + 3]);
    float acc = fmaf(V, Wh1[LL * LL + l], bh1[l]);
#pragma unroll
    for (int k = 0; k < LL; k++)
        acc = fmaf(Hs[k], Wh1[k * LL + l], acc);
    hhs[l] = tanhf(acc);
    __syncthreads();
    float acc2 = bh2[l];
#pragma unroll
    for (int k = 0; k < LL; k++)
        acc2 = fmaf(hhs[k], Wh2[k * LL + l], acc2);
    g_newH[n * LL + l] = tanhf(acc2);
}

// ---------------------------------------------------------------------------
// Kernel 5: final. Hsum = sum_n newH; out = Hsum @ Wo + bo. One 1024-thr block.
// ---------------------------------------------------------------------------
__global__ void final_kernel(const float* __restrict__ Wo,
                             const float* __restrict__ bo,
                             float* __restrict__ out) {
    __shared__ float s[1024];
    __shared__ float s_w[2];
    int t = threadIdx.x;
    int l = t & 63, r = t >> 6;           // r in 0..15
    float acc = 0.f;
#pragma unroll 8
    for (int m = 0; m < 64; m++)
        acc += g_newH[(r + 16 * m) * LL + l];
    s[t] = acc;
    __syncthreads();
    if (t < 64) {
        float h = 0.f;
#pragma unroll
        for (int q = 0; q < 16; q++) h += s[q * 64 + t];
        float v = h * Wo[t];
#pragma unroll
        for (int o = 16; o > 0; o >>= 1)
            v += __shfl_down_sync(0xffffffffu, v, o);
        if ((t & 31) == 0) s_w[t >> 5] = v;
    }
    __syncthreads();
    if (t == 0) out[0] = s_w[0] + s_w[1] + bo[0];
}

// ---------------------------------------------------------------------------
extern "C" void kernel_launch(void* const* d_in, const int* in_sizes, int n_in,
                              void* d_out, int out_size) {
    (void)in_sizes; (void)n_in; (void)out_size;
    const int*   cats   = (const int*)  d_in[0];
    const float* coords = (const float*)d_in[1];
    const float* LM     = (const float*)d_in[2];
    const float* We1    = (const float*)d_in[3];
    const float* be1    = (const float*)d_in[4];
    const float* We2    = (const float*)d_in[5];
    const float* be2    = (const float*)d_in[6];
    const float* Wh1    = (const float*)d_in[7];
    const float* bh1    = (const float*)d_in[8];
    const float* Wh2    = (const float*)d_in[9];
    const float* bh2    = (const float*)d_in[10];
    const float* Wo     = (const float*)d_in[11];
    const float* bo     = (const float*)d_in[12];

    cudaFuncSetAttribute(pair_kernel,
                         cudaFuncAttributeMaxDynamicSharedMemorySize, DYN_BYTES);

    prep_kernel  <<<NN, LL >>>(cats, LM, We1, be1);
    buildB_kernel<<<1, 256>>>(We2);
    pair_kernel  <<<2048, 256, DYN_BYTES>>>(coords, We1, be2, 0);
    pair_kernel  <<<2048, 256, DYN_BYTES>>>(coords, We1, be2, 2);
    head_kernel  <<<NN, LL >>>(cats, LM, Wh1, bh1, Wh2, bh2);
    final_kernel <<<1, 1024>>>(Wo, bo, (float*)d_out);
}

// round 11
// speedup vs baseline: 5.2529x; 1.0717x over previous
#include <cuda_runtime.h>
#include <cuda_bf16.h>
#include <cstdint>

#define NN 1024
#define LL 64

// scratch (allocation-free rule: device globals)
__device__ __align__(16) float g_preib[NN * LL];        // pre_i + be1
__device__ __align__(16) float g_prejT[32 * NN * 2];    // prej transposed: [(k>>1)][j][k&1]
__device__ float g_Vp[NN * 4];                          // per-quadrant V partials
__device__ __align__(16) float g_newH[NN * LL];
__device__ __align__(16) __nv_bfloat16 g_Bsw[LL * LL];  // We2^T bf16, SW128-swizzled

// HW tanh: 1 MUFU op
__device__ __forceinline__ float htanh(float x) {
    float y;
    asm("tanh.approx.f32 %0, %1;" : "=f"(y) : "f"(x));
    return y;
}

__device__ __forceinline__ uint32_t smem_u32(const void* p) {
    uint32_t a;
    asm("{ .reg .u64 t; cvta.to.shared.u64 t, %1; cvt.u32.u64 %0, t; }" : "=r"(a) : "l"(p));
    return a;
}
__device__ __forceinline__ void ldsm4(uint32_t* r, uint32_t addr) {
    asm volatile("ldmatrix.sync.aligned.m8n8.x4.shared.b16 {%0,%1,%2,%3}, [%4];"
                 : "=r"(r[0]), "=r"(r[1]), "=r"(r[2]), "=r"(r[3]) : "r"(addr));
}
__device__ __forceinline__ void mma16816(float* c, const uint32_t* a, const uint32_t* b) {
    asm volatile(
        "mma.sync.aligned.m16n8k16.row.col.f32.bf16.bf16.f32 "
        "{%0,%1,%2,%3},{%4,%5,%6,%7},{%8,%9},{%0,%1,%2,%3};"
        : "+f"(c[0]), "+f"(c[1]), "+f"(c[2]), "+f"(c[3])
        : "r"(a[0]), "r"(a[1]), "r"(a[2]), "r"(a[3]), "r"(b[0]), "r"(b[1]));
}
__device__ __forceinline__ uint32_t pkbf2(float a, float b) {
    __nv_bfloat162 h = __floats2bfloat162_rn(a, b);
    return *reinterpret_cast<uint32_t*>(&h);
}

// dynamic smem layout (offsets from 1024-aligned base)
#define OFF_B      0u          // 8KB (B bf16, [n][k] swizzled)
#define OFF_D2     8192u       // 1KB (d2 for 256 j's vs this block's i)
#define OFF_PW     9216u       // 512B (interleaved preib/w1z)
#define OFF_BE2    9728u       // 256B
#define DYN_BYTES  (9984u + 1024u)

// ---------------------------------------------------------------------------
// Kernel 0: blocks 0..NN-1: preib = H@We1[:L]+be1 ; prejT = (H@We1[L:2L])^T
//           block NN: build swizzled bf16 B = We2^T
// ---------------------------------------------------------------------------
__global__ void prep_kernel(const int* __restrict__ cats,
                            const float* __restrict__ LM,
                            const float* __restrict__ We1,
                            const float* __restrict__ be1,
                            const float* __restrict__ We2) {
    int n = blockIdx.x, l = threadIdx.x;
    if (n == NN) {  // buildB
        for (int idx = l; idx < LL * LL; idx += LL) {
            int nn = idx & 63, k = idx >> 6;
            float f = We2[k * LL + nn];
            uint32_t o = (uint32_t)(nn * 128 + 2 * k);
            o = o ^ ((o >> 3) & 0x70);
            *(__nv_bfloat16*)((char*)g_Bsw + o) = __float2bfloat16(f);
        }
        return;
    }
    __shared__ float Hs[LL];
    Hs[l] = LM[cats[n] * LL + l];
    __syncthreads();
    float ai = be1[l], aj = 0.0f;
#pragma unroll
    for (int k = 0; k < LL; k++) {
        float h = Hs[k];
        ai = fmaf(h, We1[k * LL + l], ai);
        aj = fmaf(h, We1[(LL + k) * LL + l], aj);
    }
    g_preib[n * LL + l] = ai;
    g_prejT[(l >> 1) * (NN * 2) + n * 2 + (l & 1)] = aj;
}

// ---------------------------------------------------------------------------
// Kernel 1: pair kernel, 4096 blocks.
// block: i = bid>>2, quad = bid&3; handles j in [quad*256, +256).
// 8 warps x 2 tiles of 16 j-rows. bf16 mma (fp32 accum) C = A @ B.
// A fragments computed directly in mma lane layout; prejT layout makes every
// fragment LDG.64 hit ONE 128B line (R10 profile: old layout = 8 lines/LDG,
// L1TEX 62%). B fragments hoisted to registers once per block.
// ---------------------------------------------------------------------------
__global__ __launch_bounds__(256, 2)
void pair_kernel(const float* __restrict__ coords,
                 const float* __restrict__ We1,
                 const float* __restrict__ be2) {
    extern __shared__ __align__(16) char dyn_raw[];
    char* base = (char*)((((uintptr_t)dyn_raw) + 1023) & ~(uintptr_t)1023);
    const uint32_t sb = smem_u32(base);

    __shared__ float s_red[8];

    float* s_d2  = (float*)(base + OFF_D2);
    float* s_pw  = (float*)(base + OFF_PW);    // [2k]=preib, [2k+1]=w1z
    float* s_be2 = (float*)(base + OFF_BE2);

    const int i    = blockIdx.x >> 2;
    const int quad = blockIdx.x & 3;
    const int jq   = quad * 256;
    const int t = threadIdx.x;
    const int w = t >> 5, lane = t & 31;

    // ---- stage pre-swizzled B (8KB copy), d2, vectors ----
    {
        const uint4* src = (const uint4*)g_Bsw;
        uint4* dst = (uint4*)(base + OFF_B);
        dst[t]       = src[t];
        dst[t + 256] = src[t + 256];
    }
    {
        const float zx = coords[3 * i], zy = coords[3 * i + 1], zz = coords[3 * i + 2];
        int j = jq + t;
        float dx = zx - coords[3 * j];
        float dy = zy - coords[3 * j + 1];
        float dz = zz - coords[3 * j + 2];
        s_d2[t] = dx * dx + dy * dy + dz * dz;
    }
    if (t < LL) {
        s_pw[2 * t]     = g_preib[i * LL + t];
        s_pw[2 * t + 1] = We1[2 * LL * LL + t];
        s_be2[t]        = be2[t];
    }
    __syncthreads();

    // ldmatrix B lane mapping (x4 covers n-pair x k-halves)
    const int brow = lane & 7;
    const int bg   = lane >> 3;
    const uint32_t bns  = (uint32_t)(bg >> 1) * 1024u;
    const uint32_t bks  = (uint32_t)(bg & 1) * 16u;
    const uint32_t xorB = (uint32_t)(brow << 4);
    const uint32_t bB   = sb + OFF_B + bns + (uint32_t)brow * 128u;

    // ---- hoist ALL B fragments into registers (once per block) ----
    uint32_t breg[4][4][4];
#pragma unroll
    for (int ntp = 0; ntp < 4; ntp++)
#pragma unroll
        for (int kk = 0; kk < 4; kk++) {
            uint32_t col = ((uint32_t)(kk * 32) + bks) ^ xorB;
            ldsm4(breg[ntp][kk], bB + (uint32_t)(ntp * 2048) + col);
        }

    // fragment lane mapping
    const int rquad = lane >> 2;           // row within tile (and +8)
    const int cpair = (lane & 3) * 2;      // col pair base
    const int cb = cpair;                  // epilogue be2 col base
    const int chb = cpair >> 1;            // prejT k-pair index base

    float vpart = 0.0f;

#pragma unroll
    for (int tt = 0; tt < 2; tt++) {
        const int tile = w + tt * 8;            // 0..15 within quadrant
        const int jloc = tile * 16;
        const int jbase = jq + jloc;

        // ---------------- phase 1: A fragments directly ----------------
        const float d2a = s_d2[jloc + rquad];
        const float d2b = s_d2[jloc + rquad + 8];
        const float* pT = g_prejT + (jbase + rquad) * 2;

        uint32_t ahi[4][4];
#pragma unroll
        for (int kk = 0; kk < 4; kk++) {
            const int c  = cpair + 16 * kk;
            const int ch = chb + 8 * kk;
            float4 pw0 = *(const float4*)&s_pw[2 * c];
            float4 pw1 = *(const float4*)&s_pw[2 * (c + 8)];
            float2 pA0 = *(const float2*)(pT + ch * (NN * 2));
            float2 pB0 = *(const float2*)(pT + ch * (NN * 2) + 16);
            float2 pA1 = *(const float2*)(pT + (ch + 4) * (NN * 2));
            float2 pB1 = *(const float2*)(pT + (ch + 4) * (NN * 2) + 16);
            ahi[kk][0] = pkbf2(htanh(fmaf(d2a, pw0.y, pw0.x + pA0.x)),
                               htanh(fmaf(d2a, pw0.w, pw0.z + pA0.y)));
            ahi[kk][1] = pkbf2(htanh(fmaf(d2b, pw0.y, pw0.x + pB0.x)),
                               htanh(fmaf(d2b, pw0.w, pw0.z + pB0.y)));
            ahi[kk][2] = pkbf2(htanh(fmaf(d2a, pw1.y, pw1.x + pA1.x)),
                               htanh(fmaf(d2a, pw1.w, pw1.z + pA1.y)));
            ahi[kk][3] = pkbf2(htanh(fmaf(d2b, pw1.y, pw1.x + pB1.x)),
                               htanh(fmaf(d2b, pw1.w, pw1.z + pB1.y)));
        }

        // ---------------- phase 2: MMAs (A and B from registers) --------
        const bool mytile = (jbase <= i) && (i < jbase + 16);
        const int rowi = i - jbase;
#pragma unroll
        for (int ntp = 0; ntp < 4; ntp++) {
            const int n0 = 2 * ntp, nx = n0 + 1;
            float c0[4] = {0.f, 0.f, 0.f, 0.f};
            float c1[4] = {0.f, 0.f, 0.f, 0.f};
#pragma unroll
            for (int kk = 0; kk < 4; kk++) {
                mma16816(c0, ahi[kk], breg[ntp][kk]);
                mma16816(c1, ahi[kk], breg[ntp][kk] + 2);
            }
            float b00 = s_be2[n0 * 8 + cb], b01 = s_be2[n0 * 8 + cb + 1];
            float b10 = s_be2[nx * 8 + cb], b11 = s_be2[nx * 8 + cb + 1];
            float acc0 = htanh(c0[0] + b00) + htanh(c0[1] + b01)
                       + htanh(c1[0] + b10) + htanh(c1[1] + b11);
            float acc1 = htanh(c0[2] + b00) + htanh(c0[3] + b01)
                       + htanh(c1[2] + b10) + htanh(c1[3] + b11);
            if (!(mytile && rquad == rowi))     vpart += acc0;
            if (!(mytile && rquad + 8 == rowi)) vpart += acc1;
        }
    }

    // reduce over warp + block -> Vp[i][quad]
#pragma unroll
    for (int o = 16; o > 0; o >>= 1)
        vpart += __shfl_down_sync(0xffffffffu, vpart, o);
    if (lane == 0) s_red[w] = vpart;
    __syncthreads();
    if (t == 0) {
        float v = 0.f;
#pragma unroll
        for (int q = 0; q < 8; q++) v += s_red[q];
        g_Vp[i * 4 + quad] = v;
    }
}

// ---------------------------------------------------------------------------
// Kernel 2: head. V = sum of 4 quadrant partials.
// ---------------------------------------------------------------------------
__global__ void head_kernel(const int* __restrict__ cats,
                            const float* __restrict__ LM,
                            const float* __restrict__ Wh1,
                            const float* __restrict__ bh1,
                            const float* __restrict__ Wh2,
                            const float* __restrict__ bh2) {
    __shared__ float Hs[LL];
    __shared__ float hhs[LL];
    int n = blockIdx.x, l = threadIdx.x;
    Hs[l] = LM[cats[n] * LL + l];
    __syncthreads();
    float V = (g_Vp[n * 4 + 0] + g_Vp[n * 4 + 1]) + (g_Vp[n * 4 + 2] + g_Vp[n * 4 + 3]);
    float acc = fmaf(V, Wh1[LL * LL + l], bh1[l]);
#pragma unroll
    for (int k = 0; k < LL; k++)
        acc = fmaf(Hs[k], Wh1[k * LL + l], acc);
    hhs[l] = tanhf(acc);
    __syncthreads();
    float acc2 = bh2[l];
#pragma unroll
    for (int k = 0; k < LL; k++)
        acc2 = fmaf(hhs[k], Wh2[k * LL + l], acc2);
    g_newH[n * LL + l] = tanhf(acc2);
}

// ---------------------------------------------------------------------------
// Kernel 3: final. Hsum = sum_n newH; out = Hsum @ Wo + bo. One 1024-thr block.
// ---------------------------------------------------------------------------
__global__ void final_kernel(const float* __restrict__ Wo,
                             const float* __restrict__ bo,
                             float* __restrict__ out) {
    __shared__ float s[1024];
    __shared__ float s_w[2];
    int t = threadIdx.x;
    int l = t & 63, r = t >> 6;           // r in 0..15
    float acc = 0.f;
#pragma unroll 8
    for (int m = 0; m < 64; m++)
        acc += g_newH[(r + 16 * m) * LL + l];
    s[t] = acc;
    __syncthreads();
    if (t < 64) {
        float h = 0.f;
#pragma unroll
        for (int q = 0; q < 16; q++) h += s[q * 64 + t];
        float v = h * Wo[t];
#pragma unroll
        for (int o = 16; o > 0; o >>= 1)
            v += __shfl_down_sync(0xffffffffu, v, o);
        if ((t & 31) == 0) s_w[t >> 5] = v;
    }
    __syncthreads();
    if (t == 0) out[0] = s_w[0] + s_w[1] + bo[0];
}

// ---------------------------------------------------------------------------
extern "C" void kernel_launch(void* const* d_in, const int* in_sizes, int n_in,
                              void* d_out, int out_size) {
    (void)in_sizes; (void)n_in; (void)out_size;
    const int*   cats   = (const int*)  d_in[0];
    const float* coords = (const float*)d_in[1];
    const float* LM     = (const float*)d_in[2];
    const float* We1    = (const float*)d_in[3];
    const float* be1    = (const float*)d_in[4];
    const float* We2    = (const float*)d_in[5];
    const float* be2    = (const float*)d_in[6];
    const float* Wh1    = (const float*)d_in[7];
    const float* bh1    = (const float*)d_in[8];
    const float* Wh2    = (const float*)d_in[9];
    const float* bh2    = (const float*)d_in[10];
    const float* Wo     = (const float*)d_in[11];
    const float* bo     = (const float*)d_in[12];

    cudaFuncSetAttribute(pair_kernel,
                         cudaFuncAttributeMaxDynamicSharedMemorySize, DYN_BYTES);

    prep_kernel <<<NN + 1, LL>>>(cats, LM, We1, be1, We2);
    pair_kernel <<<4096, 256, DYN_BYTES>>>(coords, We1, be2);
    head_kernel <<<NN, LL>>>(cats, LM, Wh1, bh1, Wh2, bh2);
    final_kernel<<<1, 1024>>>(Wo, bo, (float*)d_out);
}